// round 1
// baseline (speedup 1.0000x reference)
#include <cuda_runtime.h>
#include <math.h>

#define NN 10000
#define EE 160000
#define HH 256

// Scratch (no runtime allocation allowed)
__device__ float g_xcat[NN * 48];
__device__ float g_h[NN * HH];
__device__ float g_m[NN * HH];
__device__ float g_eattr[EE * HH];
__device__ float g_agg[NN * HH];
__device__ float g_t[NN * HH];
__device__ float g_u[NN * HH];

__device__ __forceinline__ float gelu_f(float x) {
    // jax.nn.gelu default: tanh approximation
    float x3 = x * x * x;
    return 0.5f * x * (1.0f + tanhf(0.7978845608028654f * (x + 0.044715f * x3)));
}

__device__ __forceinline__ float lrelu_f(float x) {
    return x > 0.0f ? x : 0.01f * x;
}

// ---------------------------------------------------------------------------
// Build concatenated node features [N, 48] = [emb_table[atom_types] | x_extra]
// ---------------------------------------------------------------------------
__global__ void xcat_kernel(const int* __restrict__ atom_types,
                            const float* __restrict__ x_extra,
                            const float* __restrict__ emb_table,
                            float* __restrict__ xcat, int N) {
    int idx = blockIdx.x * blockDim.x + threadIdx.x;
    if (idx < N * 48) {
        int n = idx / 48;
        int c = idx - n * 48;
        float v;
        if (c < 32) v = emb_table[atom_types[n] * 32 + c];
        else        v = x_extra[n * 16 + (c - 32)];
        xcat[idx] = v;
    }
}

// ---------------------------------------------------------------------------
// Generic GEMM: C[rows,256] = act(A[rows,K] @ W[K,256] + bias) + res
// BM=64, BN=256, BK=32, 256 threads, 4x16 accumulators/thread
// act: 0 = none, 1 = gelu
// ---------------------------------------------------------------------------
__global__ __launch_bounds__(256, 2) void gemm256(
    const float* __restrict__ A, int K,
    const float* __restrict__ W,
    const float* __restrict__ bias,
    const float* __restrict__ res,
    float* __restrict__ C, int rows, int act) {
    __shared__ float As[64 * 33];
    __shared__ float Bs[32 * 256];
    int tid = threadIdx.x;
    int tx = tid & 15, ty = tid >> 4;
    int row0 = blockIdx.x * 64;

    float acc[4][16];
#pragma unroll
    for (int i = 0; i < 4; i++)
#pragma unroll
        for (int j = 0; j < 16; j++) acc[i][j] = 0.0f;

    for (int k0 = 0; k0 < K; k0 += 32) {
#pragma unroll
        for (int i = 0; i < 8; i++) {
            int idx = tid + i * 256;
            int r = idx >> 5, c = idx & 31;
            int gr = row0 + r, gk = k0 + c;
            As[r * 33 + c] = (gr < rows && gk < K) ? A[(long)gr * K + gk] : 0.0f;
        }
#pragma unroll
        for (int i = 0; i < 32; i++) {
            int gk = k0 + i;
            Bs[i * 256 + tid] = (gk < K) ? W[(long)gk * 256 + tid] : 0.0f;
        }
        __syncthreads();
#pragma unroll
        for (int kk = 0; kk < 32; kk++) {
            float a[4];
#pragma unroll
            for (int i = 0; i < 4; i++) a[i] = As[(ty * 4 + i) * 33 + kk];
#pragma unroll
            for (int j = 0; j < 16; j++) {
                float b = Bs[kk * 256 + tx + 16 * j];
#pragma unroll
                for (int i = 0; i < 4; i++) acc[i][j] = fmaf(a[i], b, acc[i][j]);
            }
        }
        __syncthreads();
    }

#pragma unroll
    for (int i = 0; i < 4; i++) {
        int r = row0 + ty * 4 + i;
        if (r < rows) {
#pragma unroll
            for (int j = 0; j < 16; j++) {
                int col = tx + 16 * j;
                float v = acc[i][j];
                if (bias) v += bias[col];
                if (act == 1) v = gelu_f(v);
                if (res) v += res[(long)r * 256 + col];
                C[(long)r * 256 + col] = v;
            }
        }
    }
}

// ---------------------------------------------------------------------------
// edge_attr[E,256] = (envelope(d) * sin(freq*d)) @ w_r2m + b_r2m
// ---------------------------------------------------------------------------
__global__ __launch_bounds__(256, 2) void edge_attr_kernel(
    const float* __restrict__ dists, const float* __restrict__ freq,
    const float* __restrict__ Wr, const float* __restrict__ br,
    float* __restrict__ eattr, int E) {
    __shared__ float Rs[64 * 33];
    __shared__ float Bs[32 * 256];
    __shared__ float s_freq[32];
    int tid = threadIdx.x;
    int tx = tid & 15, ty = tid >> 4;
    int e0 = blockIdx.x * 64;

    if (tid < 32) s_freq[tid] = freq[tid];
#pragma unroll
    for (int i = 0; i < 32; i++) Bs[i * 256 + tid] = Wr[i * 256 + tid];
    __syncthreads();

#pragma unroll
    for (int i = 0; i < 8; i++) {
        int idx = tid + i * 256;
        int el = idx >> 5, r = idx & 31;
        int e = e0 + el;
        float d = (e < E) ? dists[e] * 0.2f : 1.0f;  // d / CUTOFF
        float d2 = d * d;
        float d5 = d2 * d2 * d;
        // P=6: env = 1/d - 28 d^5 + 48 d^6 - 21 d^7
        float env = 1.0f / d + d5 * (-28.0f + d * (48.0f + d * (-21.0f)));
        Rs[el * 33 + r] = env * sinf(s_freq[r] * d);
    }
    __syncthreads();

    float acc[4][16];
#pragma unroll
    for (int i = 0; i < 4; i++)
#pragma unroll
        for (int j = 0; j < 16; j++) acc[i][j] = 0.0f;

#pragma unroll
    for (int kk = 0; kk < 32; kk++) {
        float a[4];
#pragma unroll
        for (int i = 0; i < 4; i++) a[i] = Rs[(ty * 4 + i) * 33 + kk];
#pragma unroll
        for (int j = 0; j < 16; j++) {
            float b = Bs[kk * 256 + tx + 16 * j];
#pragma unroll
            for (int i = 0; i < 4; i++) acc[i][j] = fmaf(a[i], b, acc[i][j]);
        }
    }

#pragma unroll
    for (int i = 0; i < 4; i++) {
        int e = e0 + ty * 4 + i;
        if (e < E) {
#pragma unroll
            for (int j = 0; j < 16; j++) {
                int col = tx + 16 * j;
                eattr[(long)e * 256 + col] = acc[i][j] + br[col];
            }
        }
    }
}

// ---------------------------------------------------------------------------
// Fused edge MLP: concat(m[src], m[dst], edge_attr) -> 4 layers -> scatter add
// One block = 64 edges. Dynamic smem: As(64x33) + Bs(32x256) + act(64x257)
// ---------------------------------------------------------------------------
__global__ __launch_bounds__(256, 2) void edge_mlp_kernel(
    const float* __restrict__ m, const float* __restrict__ eattr,
    const int* __restrict__ edge_index,
    const float* __restrict__ W1, const float* __restrict__ b1,
    const float* __restrict__ W2, const float* __restrict__ b2,
    const float* __restrict__ W3, const float* __restrict__ b3,
    const float* __restrict__ W4, const float* __restrict__ b4,
    float* __restrict__ agg, int E) {
    extern __shared__ float sm[];
    float* As = sm;                    // 64*33  = 2112
    float* Bs = sm + 64 * 33;          // 32*256 = 8192
    float* act_s = Bs + 32 * 256;      // 64*257 = 16448
    __shared__ int s_src[64], s_dst[64];

    int tid = threadIdx.x;
    int tx = tid & 15, ty = tid >> 4;
    int e0 = blockIdx.x * 64;

    if (tid < 64) {
        int e = e0 + tid;
        s_src[tid] = (e < E) ? edge_index[e] : 0;
        s_dst[tid] = (e < E) ? edge_index[E + e] : 0;
    }
    __syncthreads();

    float acc[4][16];
#pragma unroll
    for (int i = 0; i < 4; i++)
#pragma unroll
        for (int j = 0; j < 16; j++) acc[i][j] = 0.0f;

    // ---- Layer 1: K = 768 (m[src] | m[dst] | edge_attr) ----
    for (int t = 0; t < 24; t++) {
        int k0 = t * 32;
#pragma unroll
        for (int i = 0; i < 8; i++) {
            int idx = tid + i * 256;
            int r = idx >> 5, c = idx & 31;
            int k = k0 + c;
            int e = e0 + r;
            float v = 0.0f;
            if (e < E) {
                if (k < 256)      v = m[(long)s_src[r] * 256 + k];
                else if (k < 512) v = m[(long)s_dst[r] * 256 + (k - 256)];
                else              v = eattr[(long)e * 256 + (k - 512)];
            }
            As[r * 33 + c] = v;
        }
#pragma unroll
        for (int i = 0; i < 32; i++)
            Bs[i * 256 + tid] = W1[(long)(k0 + i) * 256 + tid];
        __syncthreads();
#pragma unroll
        for (int kk = 0; kk < 32; kk++) {
            float a[4];
#pragma unroll
            for (int i = 0; i < 4; i++) a[i] = As[(ty * 4 + i) * 33 + kk];
#pragma unroll
            for (int j = 0; j < 16; j++) {
                float b = Bs[kk * 256 + tx + 16 * j];
#pragma unroll
                for (int i = 0; i < 4; i++) acc[i][j] = fmaf(a[i], b, acc[i][j]);
            }
        }
        __syncthreads();
    }
    // bias + lrelu -> act_s
#pragma unroll
    for (int i = 0; i < 4; i++) {
        int r = ty * 4 + i;
#pragma unroll
        for (int j = 0; j < 16; j++) {
            int col = tx + 16 * j;
            act_s[r * 257 + col] = lrelu_f(acc[i][j] + b1[col]);
        }
    }
    __syncthreads();

    // ---- Layers 2 and 3 (K=256, act from smem, in-place update) ----
    const float* Ws[2] = {W2, W3};
    const float* bsl[2] = {b2, b3};
    for (int L = 0; L < 2; L++) {
#pragma unroll
        for (int i = 0; i < 4; i++)
#pragma unroll
            for (int j = 0; j < 16; j++) acc[i][j] = 0.0f;
        for (int t = 0; t < 8; t++) {
            int k0 = t * 32;
#pragma unroll
            for (int i = 0; i < 32; i++)
                Bs[i * 256 + tid] = Ws[L][(long)(k0 + i) * 256 + tid];
            __syncthreads();
#pragma unroll
            for (int kk = 0; kk < 32; kk++) {
                float a[4];
#pragma unroll
                for (int i = 0; i < 4; i++) a[i] = act_s[(ty * 4 + i) * 257 + k0 + kk];
#pragma unroll
                for (int j = 0; j < 16; j++) {
                    float b = Bs[kk * 256 + tx + 16 * j];
#pragma unroll
                    for (int i = 0; i < 4; i++) acc[i][j] = fmaf(a[i], b, acc[i][j]);
                }
            }
            __syncthreads();
        }
#pragma unroll
        for (int i = 0; i < 4; i++) {
            int r = ty * 4 + i;
#pragma unroll
            for (int j = 0; j < 16; j++) {
                int col = tx + 16 * j;
                act_s[r * 257 + col] = lrelu_f(acc[i][j] + bsl[L][col]);
            }
        }
        __syncthreads();
    }

    // ---- Layer 4 (no activation) + scatter-add to agg[dst] ----
#pragma unroll
    for (int i = 0; i < 4; i++)
#pragma unroll
        for (int j = 0; j < 16; j++) acc[i][j] = 0.0f;
    for (int t = 0; t < 8; t++) {
        int k0 = t * 32;
#pragma unroll
        for (int i = 0; i < 32; i++)
            Bs[i * 256 + tid] = W4[(long)(k0 + i) * 256 + tid];
        __syncthreads();
#pragma unroll
        for (int kk = 0; kk < 32; kk++) {
            float a[4];
#pragma unroll
            for (int i = 0; i < 4; i++) a[i] = act_s[(ty * 4 + i) * 257 + k0 + kk];
#pragma unroll
            for (int j = 0; j < 16; j++) {
                float b = Bs[kk * 256 + tx + 16 * j];
#pragma unroll
                for (int i = 0; i < 4; i++) acc[i][j] = fmaf(a[i], b, acc[i][j]);
            }
        }
        __syncthreads();
    }
#pragma unroll
    for (int i = 0; i < 4; i++) {
        int r = ty * 4 + i;
        int e = e0 + r;
        if (e < E) {
            int d = s_dst[r];
#pragma unroll
            for (int j = 0; j < 16; j++) {
                int col = tx + 16 * j;
                atomicAdd(&agg[(long)d * 256 + col], acc[i][j] + b4[col]);
            }
        }
    }
}

// ---------------------------------------------------------------------------
extern "C" void kernel_launch(void* const* d_in, const int* in_sizes, int n_in,
                              void* d_out, int out_size) {
    const int* atom_types = (const int*)d_in[0];
    const float* x_extra = (const float*)d_in[1];
    const int* edge_index = (const int*)d_in[2];
    const float* dists = (const float*)d_in[3];
    const float* freq = (const float*)d_in[4];
    const float* emb_table = (const float*)d_in[5];
    const float* w_emb = (const float*)d_in[6];
    const float* b_emb = (const float*)d_in[7];
    const float* w_n2m = (const float*)d_in[8];
    const float* b_n2m = (const float*)d_in[9];
    const float* w_r2m = (const float*)d_in[10];
    const float* b_r2m = (const float*)d_in[11];
    const float* w_m2n = (const float*)d_in[12];
    const float* mw1 = (const float*)d_in[13];
    const float* mb1 = (const float*)d_in[14];
    const float* mw2 = (const float*)d_in[15];
    const float* mb2 = (const float*)d_in[16];
    const float* mw3 = (const float*)d_in[17];
    const float* mb3 = (const float*)d_in[18];
    const float* mw4 = (const float*)d_in[19];
    const float* mb4 = (const float*)d_in[20];
    const float* fw1 = (const float*)d_in[21];
    const float* fb1 = (const float*)d_in[22];
    const float* fw2 = (const float*)d_in[23];
    const float* fb2 = (const float*)d_in[24];
    float* out = (float*)d_out;

    int N = in_sizes[0];
    int E = in_sizes[2] / 2;

    float *p_xcat, *p_h, *p_m, *p_eattr, *p_agg, *p_t, *p_u;
    cudaGetSymbolAddress((void**)&p_xcat, g_xcat);
    cudaGetSymbolAddress((void**)&p_h, g_h);
    cudaGetSymbolAddress((void**)&p_m, g_m);
    cudaGetSymbolAddress((void**)&p_eattr, g_eattr);
    cudaGetSymbolAddress((void**)&p_agg, g_agg);
    cudaGetSymbolAddress((void**)&p_t, g_t);
    cudaGetSymbolAddress((void**)&p_u, g_u);

    const size_t EDGE_SMEM = (size_t)(64 * 33 + 32 * 256 + 64 * 257) * sizeof(float);
    cudaFuncSetAttribute(edge_mlp_kernel,
                         cudaFuncAttributeMaxDynamicSharedMemorySize,
                         (int)EDGE_SMEM);

    int gN = (N + 63) / 64;
    int gE = (E + 63) / 64;

    xcat_kernel<<<(N * 48 + 255) / 256, 256>>>(atom_types, x_extra, emb_table, p_xcat, N);
    gemm256<<<gN, 256>>>(p_xcat, 48, w_emb, b_emb, nullptr, p_h, N, 1);        // h = gelu(xcat@w_emb+b)
    gemm256<<<gN, 256>>>(p_h, 256, w_n2m, b_n2m, nullptr, p_m, N, 0);          // m = h@w_n2m+b
    edge_attr_kernel<<<gE, 256>>>(dists, freq, w_r2m, b_r2m, p_eattr, E);
    cudaMemsetAsync(p_agg, 0, (size_t)N * 256 * sizeof(float));
    edge_mlp_kernel<<<gE, 256, EDGE_SMEM>>>(p_m, p_eattr, edge_index,
                                            mw1, mb1, mw2, mb2, mw3, mb3, mw4, mb4,
                                            p_agg, E);
    gemm256<<<gN, 256>>>(p_agg, 256, w_m2n, nullptr, p_h, p_t, N, 0);          // t = h + agg@w_m2n
    gemm256<<<gN, 256>>>(p_t, 256, fw1, fb1, nullptr, p_u, N, 1);              // u = gelu(t@fc_w1+b)
    gemm256<<<gN, 256>>>(p_u, 256, fw2, fb2, p_t, out, N, 0);                  // out = t + u@fc_w2+b
}

// round 4
// speedup vs baseline: 1.9517x; 1.9517x over previous
#include <cuda_runtime.h>
#include <cuda_bf16.h>
#include <math.h>
#include <stdint.h>

#define NN 10000
#define EE 160000
#define HH 256

// ---------------------------------------------------------------------------
// Scratch (no runtime allocation allowed)
// ---------------------------------------------------------------------------
__device__ float g_xcat[NN * 48];
__device__ float g_h[NN * HH];
__device__ float g_m[NN * HH];
__device__ float g_agg[NN * HH];
__device__ float g_t[NN * HH];
__device__ float g_u[NN * HH];
// bf16 hi/lo operands for tensor-core path
__device__ __nv_bfloat16 g_mh[NN * HH];
__device__ __nv_bfloat16 g_ml[NN * HH];
__device__ __nv_bfloat16 g_eah[(size_t)EE * HH];
__device__ __nv_bfloat16 g_eal[(size_t)EE * HH];
// Transposed weights W^T[N=256, K] K-major, tiled per Kc=32 chunk.
// 48 tiles (L1: 0..23, L2: 24..31, L3: 32..39, L4: 40..47)
// tile = 8192 bf16 hi (n*32+kk) followed by 8192 bf16 lo
__device__ __align__(16) __nv_bfloat16 g_wt[48 * 16384];

__device__ __forceinline__ float gelu_f(float x) {
    float x3 = x * x * x;
    return 0.5f * x * (1.0f + tanhf(0.7978845608028654f * (x + 0.044715f * x3)));
}
__device__ __forceinline__ float lrelu_f(float x) { return x > 0.0f ? x : 0.01f * x; }

// ---------------------------------------------------------------------------
// PTX helpers (sm_80-family: valid at .target sm_100)
// ---------------------------------------------------------------------------
__device__ __forceinline__ uint32_t smem_u32(const void* p) {
    uint32_t a;
    asm("{ .reg .u64 t; cvta.to.shared.u64 t, %1; cvt.u32.u64 %0, t; }" : "=r"(a) : "l"(p));
    return a;
}
__device__ __forceinline__ void cp_async16(uint32_t smem_addr, const void* gptr) {
    asm volatile("cp.async.cg.shared.global [%0], [%1], 16;\n" :: "r"(smem_addr), "l"(gptr));
}
#define CP_COMMIT() asm volatile("cp.async.commit_group;\n" ::: "memory")
#define CP_WAIT0()  asm volatile("cp.async.wait_group 0;\n" ::: "memory")
#define CP_WAIT1()  asm volatile("cp.async.wait_group 1;\n" ::: "memory")

__device__ __forceinline__ void ldsm4(uint32_t* f, uint32_t a) {
    asm volatile("ldmatrix.sync.aligned.m8n8.x4.shared.b16 {%0,%1,%2,%3}, [%4];\n"
                 : "=r"(f[0]), "=r"(f[1]), "=r"(f[2]), "=r"(f[3]) : "r"(a));
}
__device__ __forceinline__ void mma16816(float* d, const uint32_t* a, uint32_t b0, uint32_t b1) {
    asm volatile(
        "mma.sync.aligned.m16n8k16.row.col.f32.bf16.bf16.f32 "
        "{%0,%1,%2,%3}, {%4,%5,%6,%7}, {%8,%9}, {%0,%1,%2,%3};\n"
        : "+f"(d[0]), "+f"(d[1]), "+f"(d[2]), "+f"(d[3])
        : "r"(a[0]), "r"(a[1]), "r"(a[2]), "r"(a[3]), "r"(b0), "r"(b1));
}

// ---------------------------------------------------------------------------
// Prep kernels + fp32 node-side GEMM (proven in R1)
// ---------------------------------------------------------------------------
__global__ void xcat_kernel(const int* __restrict__ atom_types,
                            const float* __restrict__ x_extra,
                            const float* __restrict__ emb_table,
                            float* __restrict__ xcat, int N) {
    int idx = blockIdx.x * blockDim.x + threadIdx.x;
    if (idx < N * 48) {
        int n = idx / 48, c = idx - n * 48;
        xcat[idx] = (c < 32) ? emb_table[atom_types[n] * 32 + c] : x_extra[n * 16 + (c - 32)];
    }
}

__global__ __launch_bounds__(256, 2) void gemm256(
    const float* __restrict__ A, int K, const float* __restrict__ W,
    const float* __restrict__ bias, const float* __restrict__ res,
    float* __restrict__ C, int rows, int act) {
    __shared__ float As[64 * 33];
    __shared__ float Bs[32 * 256];
    int tid = threadIdx.x, tx = tid & 15, ty = tid >> 4;
    int row0 = blockIdx.x * 64;
    float acc[4][16];
#pragma unroll
    for (int i = 0; i < 4; i++)
#pragma unroll
        for (int j = 0; j < 16; j++) acc[i][j] = 0.0f;
    for (int k0 = 0; k0 < K; k0 += 32) {
#pragma unroll
        for (int i = 0; i < 8; i++) {
            int idx = tid + i * 256, r = idx >> 5, c = idx & 31;
            int gr = row0 + r, gk = k0 + c;
            As[r * 33 + c] = (gr < rows && gk < K) ? A[(long)gr * K + gk] : 0.0f;
        }
#pragma unroll
        for (int i = 0; i < 32; i++) {
            int gk = k0 + i;
            Bs[i * 256 + tid] = (gk < K) ? W[(long)gk * 256 + tid] : 0.0f;
        }
        __syncthreads();
#pragma unroll
        for (int kk = 0; kk < 32; kk++) {
            float a[4];
#pragma unroll
            for (int i = 0; i < 4; i++) a[i] = As[(ty * 4 + i) * 33 + kk];
#pragma unroll
            for (int j = 0; j < 16; j++) {
                float b = Bs[kk * 256 + tx + 16 * j];
#pragma unroll
                for (int i = 0; i < 4; i++) acc[i][j] = fmaf(a[i], b, acc[i][j]);
            }
        }
        __syncthreads();
    }
#pragma unroll
    for (int i = 0; i < 4; i++) {
        int r = row0 + ty * 4 + i;
        if (r < rows) {
#pragma unroll
            for (int j = 0; j < 16; j++) {
                int col = tx + 16 * j;
                float v = acc[i][j];
                if (bias) v += bias[col];
                if (act == 1) v = gelu_f(v);
                if (res) v += res[(long)r * 256 + col];
                C[(long)r * 256 + col] = v;
            }
        }
    }
}

// eattr = rbf @ w_r2m + b_r2m, emitted as bf16 hi/lo
__global__ __launch_bounds__(256, 2) void edge_attr_kernel(
    const float* __restrict__ dists, const float* __restrict__ freq,
    const float* __restrict__ Wr, const float* __restrict__ br,
    __nv_bfloat16* __restrict__ eah, __nv_bfloat16* __restrict__ eal, int E) {
    __shared__ float Rs[64 * 33];
    __shared__ float Bs[32 * 256];
    __shared__ float s_freq[32];
    int tid = threadIdx.x, tx = tid & 15, ty = tid >> 4;
    int e0 = blockIdx.x * 64;
    if (tid < 32) s_freq[tid] = freq[tid];
#pragma unroll
    for (int i = 0; i < 32; i++) Bs[i * 256 + tid] = Wr[i * 256 + tid];
    __syncthreads();
#pragma unroll
    for (int i = 0; i < 8; i++) {
        int idx = tid + i * 256, el = idx >> 5, r = idx & 31;
        int e = e0 + el;
        float d = (e < E) ? dists[e] * 0.2f : 1.0f;
        float d2 = d * d, d5 = d2 * d2 * d;
        float env = 1.0f / d + d5 * (-28.0f + d * (48.0f + d * (-21.0f)));
        Rs[el * 33 + r] = env * sinf(s_freq[r] * d);
    }
    __syncthreads();
    float acc[4][16];
#pragma unroll
    for (int i = 0; i < 4; i++)
#pragma unroll
        for (int j = 0; j < 16; j++) acc[i][j] = 0.0f;
#pragma unroll
    for (int kk = 0; kk < 32; kk++) {
        float a[4];
#pragma unroll
        for (int i = 0; i < 4; i++) a[i] = Rs[(ty * 4 + i) * 33 + kk];
#pragma unroll
        for (int j = 0; j < 16; j++) {
            float b = Bs[kk * 256 + tx + 16 * j];
#pragma unroll
            for (int i = 0; i < 4; i++) acc[i][j] = fmaf(a[i], b, acc[i][j]);
        }
    }
#pragma unroll
    for (int i = 0; i < 4; i++) {
        int e = e0 + ty * 4 + i;
        if (e < E) {
#pragma unroll
            for (int j = 0; j < 16; j++) {
                int col = tx + 16 * j;
                float v = acc[i][j] + br[col];
                __nv_bfloat16 h = __float2bfloat16(v);
                eah[(size_t)e * 256 + col] = h;
                eal[(size_t)e * 256 + col] = __float2bfloat16(v - __bfloat162float(h));
            }
        }
    }
}

// m (fp32) -> hi/lo bf16
__global__ void mprep_kernel(const float* __restrict__ m,
                             __nv_bfloat16* __restrict__ mh,
                             __nv_bfloat16* __restrict__ ml, int total) {
    int i = blockIdx.x * blockDim.x + threadIdx.x;
    if (i < total) {
        float v = m[i];
        __nv_bfloat16 h = __float2bfloat16(v);
        mh[i] = h;
        ml[i] = __float2bfloat16(v - __bfloat162float(h));
    }
}

// weights -> W^T hi/lo chunk tiles
__global__ void wprep_kernel(const float* __restrict__ w1, const float* __restrict__ w2,
                             const float* __restrict__ w3, const float* __restrict__ w4,
                             __nv_bfloat16* __restrict__ wt) {
    int id = blockIdx.x * blockDim.x + threadIdx.x;
    if (id >= 1536 * 256) return;
    int kg = id >> 8, n = id & 255;
    const float* w;
    int kl, t;
    if (kg < 768)       { w = w1; kl = kg;        t = kl >> 5; }
    else if (kg < 1024) { w = w2; kl = kg - 768;  t = 24 + (kl >> 5); }
    else if (kg < 1280) { w = w3; kl = kg - 1024; t = 32 + (kl >> 5); }
    else                { w = w4; kl = kg - 1280; t = 40 + (kl >> 5); }
    int kk = kl & 31;
    float v = w[(long)kl * 256 + n];
    __nv_bfloat16 h = __float2bfloat16(v);
    __nv_bfloat16 l = __float2bfloat16(v - __bfloat162float(h));
    size_t base = (size_t)t * 16384 + n * 32 + kk;
    wt[base] = h;
    wt[base + 8192] = l;
}

// ---------------------------------------------------------------------------
// HMMA fused edge MLP. CTA = 64 edges x 256 outputs, 8 warps (2x4 warp grid),
// warp tile 32x64, mma.sync m16n8k16 bf16 hi/lo (3 products), fp32 acc.
// Dynamic SMEM layout:
//   ACT_HI [0,       33792)  : 64 rows x 264 bf16 (stride 528B)
//   ACT_LO [33792,   67584)
//   BBUF   [67584,  149504)  : 2 x (hi 256x40 bf16 stride 80B | lo +20480)
//   ASTG   [149504, 169984)  : 2 x (hi 64x40 stride 80B | lo +5120)  (layer 1)
// ---------------------------------------------------------------------------
#define ACT_HI 0
#define ACT_LO 33792
#define BBUF   67584
#define ASTG   149504
#define DSMEM  169984

__global__ __launch_bounds__(256) void edge_mlp_hmma(
    const __nv_bfloat16* __restrict__ mh, const __nv_bfloat16* __restrict__ ml,
    const __nv_bfloat16* __restrict__ eah, const __nv_bfloat16* __restrict__ eal,
    const int* __restrict__ edge_index, const __nv_bfloat16* __restrict__ wt,
    const float* __restrict__ b1, const float* __restrict__ b2,
    const float* __restrict__ b3, const float* __restrict__ b4,
    float* __restrict__ agg, int E) {
    extern __shared__ __align__(16) char dsm[];
    __shared__ int s_src[64], s_dst[64];
    __shared__ float s_bias[1024];

    const int tid = threadIdx.x;
    const int wid = tid >> 5, lane = tid & 31;
    const int wm = wid >> 2, wn = wid & 3;
    const int r0 = wm * 32;        // warp row base (edges within block)
    const int c0 = wn * 64;        // warp col base (output channels)
    const int e0 = blockIdx.x * 64;
    const uint32_t sb = smem_u32(dsm);

    for (int i = tid; i < 1024; i += 256) {
        const float* b = (i < 256) ? b1 : (i < 512) ? b2 : (i < 768) ? b3 : b4;
        s_bias[i] = b[i & 255];
    }
    if (tid < 64) {
        int e = e0 + tid;
        s_src[tid] = (e < E) ? edge_index[e] : 0;
        s_dst[tid] = (e < E) ? edge_index[E + e] : 0;
    }
    __syncthreads();

    float acc[2][8][4];
#pragma unroll
    for (int mt = 0; mt < 2; mt++)
#pragma unroll
        for (int nt = 0; nt < 8; nt++)
#pragma unroll
            for (int i = 0; i < 4; i++) acc[mt][nt][i] = 0.0f;

    // ---- helpers as lambdas ----
    auto prefetchB = [&](int t, int buf) {
        const char* wsrc = (const char*)wt + (size_t)t * 32768;
        uint32_t dbase = sb + BBUF + buf * 40960;
#pragma unroll
        for (int it = 0; it < 8; it++) {
            int id = tid + it * 256;
            int n = id & 255, rest = id >> 8;
            int seg = rest & 3, hl = rest >> 2;
            cp_async16(dbase + hl * 20480 + n * 80 + seg * 16,
                       wsrc + hl * 16384 + n * 64 + seg * 16);
        }
    };
    auto prefetchA = [&](int c, int buf) {
        uint32_t dbase = sb + ASTG + buf * 10240;
#pragma unroll
        for (int it = 0; it < 2; it++) {
            int id = tid + it * 256;
            int row = id & 63, rest = id >> 6;
            int hl = rest & 1, seg = rest >> 1;
            const __nv_bfloat16* sp;
            if (c < 8)       sp = (hl ? ml : mh) + (size_t)s_src[row] * 256 + c * 32 + seg * 8;
            else if (c < 16) sp = (hl ? ml : mh) + (size_t)s_dst[row] * 256 + (c - 8) * 32 + seg * 8;
            else {
                int e = e0 + row;
                sp = (hl ? eal : eah) + (size_t)(e < E ? e : 0) * 256 + (c - 16) * 32 + seg * 8;
            }
            cp_async16(dbase + hl * 5120 + row * 80 + seg * 16, sp);
        }
    };
    auto compute = [&](uint32_t abase, int astride, int alo_off, uint32_t bbase) {
#pragma unroll
        for (int s = 0; s < 2; s++) {
            int ko2 = s * 32;  // k16-step byte offset
            uint32_t ah[2][4], al[2][4];
#pragma unroll
            for (int mt = 0; mt < 2; mt++) {
                uint32_t ad = abase + (uint32_t)(r0 + mt * 16 + (lane & 15)) * astride +
                              ko2 + ((lane >> 4) << 4);
                ldsm4(ah[mt], ad);
                ldsm4(al[mt], ad + alo_off);
            }
            uint32_t bh[4][4], bl[4][4];
#pragma unroll
            for (int q = 0; q < 4; q++) {
                int n = c0 + q * 16 + (lane & 7) + ((lane & 16) >> 1);
                uint32_t bd = bbase + (uint32_t)n * 80 + ko2 + ((lane & 8) << 1);
                ldsm4(bh[q], bd);
                ldsm4(bl[q], bd + 20480);
            }
#pragma unroll
            for (int mt = 0; mt < 2; mt++)
#pragma unroll
                for (int nt = 0; nt < 8; nt++)
                    mma16816(acc[mt][nt], ah[mt], bh[nt >> 1][(nt & 1) * 2], bh[nt >> 1][(nt & 1) * 2 + 1]);
#pragma unroll
            for (int mt = 0; mt < 2; mt++)
#pragma unroll
                for (int nt = 0; nt < 8; nt++)
                    mma16816(acc[mt][nt], al[mt], bh[nt >> 1][(nt & 1) * 2], bh[nt >> 1][(nt & 1) * 2 + 1]);
#pragma unroll
            for (int mt = 0; mt < 2; mt++)
#pragma unroll
                for (int nt = 0; nt < 8; nt++)
                    mma16816(acc[mt][nt], ah[mt], bl[nt >> 1][(nt & 1) * 2], bl[nt >> 1][(nt & 1) * 2 + 1]);
        }
    };
    auto epilogue_act = [&](int bidx) {
#pragma unroll
        for (int mt = 0; mt < 2; mt++) {
#pragma unroll
            for (int nt = 0; nt < 8; nt++) {
                int ra = r0 + mt * 16 + (lane >> 2);
                int ca = c0 + nt * 8 + 2 * (lane & 3);
                float bv0 = s_bias[bidx * 256 + ca], bv1 = s_bias[bidx * 256 + ca + 1];
#pragma unroll
                for (int half = 0; half < 2; half++) {
                    int r = ra + half * 8;
                    float v0 = lrelu_f(acc[mt][nt][half * 2 + 0] + bv0);
                    float v1 = lrelu_f(acc[mt][nt][half * 2 + 1] + bv1);
                    __nv_bfloat16 h0 = __float2bfloat16(v0);
                    __nv_bfloat16 h1 = __float2bfloat16(v1);
                    __nv_bfloat162 hp; hp.x = h0; hp.y = h1;
                    __nv_bfloat162 lp;
                    lp.x = __float2bfloat16(v0 - __bfloat162float(h0));
                    lp.y = __float2bfloat16(v1 - __bfloat162float(h1));
                    uint32_t off = (uint32_t)r * 528 + (uint32_t)ca * 2;
                    *(__nv_bfloat162*)(dsm + ACT_HI + off) = hp;
                    *(__nv_bfloat162*)(dsm + ACT_LO + off) = lp;
                    acc[mt][nt][half * 2 + 0] = 0.0f;
                    acc[mt][nt][half * 2 + 1] = 0.0f;
                }
            }
        }
    };

    // ================= LAYER 1: K=768, 24 chunks of 32 =================
    prefetchB(0, 0);
    prefetchA(0, 0);
    CP_COMMIT();
    for (int c = 0; c < 24; c++) {
        if (c < 23) {
            prefetchB(c + 1, (c + 1) & 1);
            prefetchA(c + 1, (c + 1) & 1);
            CP_COMMIT();
            CP_WAIT1();
        } else {
            CP_WAIT0();
        }
        __syncthreads();
        compute(sb + ASTG + (c & 1) * 10240, 80, 5120, sb + BBUF + (c & 1) * 40960);
        __syncthreads();
    }
    epilogue_act(0);
    __syncthreads();

    // ================= LAYERS 2..4: K=256, 8 chunks each =================
    for (int L = 0; L < 3; L++) {
        int t0 = 24 + L * 8;
        prefetchB(t0, 0);
        CP_COMMIT();
        for (int c = 0; c < 8; c++) {
            if (c < 7) {
                prefetchB(t0 + c + 1, (c + 1) & 1);
                CP_COMMIT();
                CP_WAIT1();
            } else {
                CP_WAIT0();
            }
            __syncthreads();
            compute(sb + ACT_HI + (uint32_t)c * 64, 528, ACT_LO - ACT_HI,
                    sb + BBUF + (c & 1) * 40960);
            __syncthreads();
        }
        if (L < 2) {
            epilogue_act(L + 1);
            __syncthreads();
        } else {
            // final: bias + scatter-add
#pragma unroll
            for (int mt = 0; mt < 2; mt++) {
#pragma unroll
                for (int nt = 0; nt < 8; nt++) {
                    int ra = r0 + mt * 16 + (lane >> 2);
                    int ca = c0 + nt * 8 + 2 * (lane & 3);
                    float bv0 = s_bias[768 + ca], bv1 = s_bias[768 + ca + 1];
#pragma unroll
                    for (int half = 0; half < 2; half++) {
                        int r = ra + half * 8;
                        int e = e0 + r;
                        if (e < E) {
                            int dn = s_dst[r];
                            atomicAdd(&agg[(size_t)dn * 256 + ca], acc[mt][nt][half * 2 + 0] + bv0);
                            atomicAdd(&agg[(size_t)dn * 256 + ca + 1], acc[mt][nt][half * 2 + 1] + bv1);
                        }
                    }
                }
            }
        }
    }
}

// ---------------------------------------------------------------------------
extern "C" void kernel_launch(void* const* d_in, const int* in_sizes, int n_in,
                              void* d_out, int out_size) {
    const int* atom_types = (const int*)d_in[0];
    const float* x_extra = (const float*)d_in[1];
    const int* edge_index = (const int*)d_in[2];
    const float* dists = (const float*)d_in[3];
    const float* freq = (const float*)d_in[4];
    const float* emb_table = (const float*)d_in[5];
    const float* w_emb = (const float*)d_in[6];
    const float* b_emb = (const float*)d_in[7];
    const float* w_n2m = (const float*)d_in[8];
    const float* b_n2m = (const float*)d_in[9];
    const float* w_r2m = (const float*)d_in[10];
    const float* b_r2m = (const float*)d_in[11];
    const float* w_m2n = (const float*)d_in[12];
    const float* mw1 = (const float*)d_in[13];
    const float* mb1 = (const float*)d_in[14];
    const float* mw2 = (const float*)d_in[15];
    const float* mb2 = (const float*)d_in[16];
    const float* mw3 = (const float*)d_in[17];
    const float* mb3 = (const float*)d_in[18];
    const float* mw4 = (const float*)d_in[19];
    const float* mb4 = (const float*)d_in[20];
    const float* fw1 = (const float*)d_in[21];
    const float* fb1 = (const float*)d_in[22];
    const float* fw2 = (const float*)d_in[23];
    const float* fb2 = (const float*)d_in[24];
    float* out = (float*)d_out;

    int N = in_sizes[0];
    int E = in_sizes[2] / 2;

    float *p_xcat, *p_h, *p_m, *p_agg, *p_t, *p_u;
    __nv_bfloat16 *p_mh, *p_ml, *p_eah, *p_eal, *p_wt;
    cudaGetSymbolAddress((void**)&p_xcat, g_xcat);
    cudaGetSymbolAddress((void**)&p_h, g_h);
    cudaGetSymbolAddress((void**)&p_m, g_m);
    cudaGetSymbolAddress((void**)&p_agg, g_agg);
    cudaGetSymbolAddress((void**)&p_t, g_t);
    cudaGetSymbolAddress((void**)&p_u, g_u);
    cudaGetSymbolAddress((void**)&p_mh, g_mh);
    cudaGetSymbolAddress((void**)&p_ml, g_ml);
    cudaGetSymbolAddress((void**)&p_eah, g_eah);
    cudaGetSymbolAddress((void**)&p_eal, g_eal);
    cudaGetSymbolAddress((void**)&p_wt, g_wt);

    cudaFuncSetAttribute(edge_mlp_hmma, cudaFuncAttributeMaxDynamicSharedMemorySize, DSMEM);

    int gN = (N + 63) / 64;
    int gE64 = (E + 63) / 64;

    wprep_kernel<<<(1536 * 256 + 255) / 256, 256>>>(mw1, mw2, mw3, mw4, p_wt);
    xcat_kernel<<<(N * 48 + 255) / 256, 256>>>(atom_types, x_extra, emb_table, p_xcat, N);
    gemm256<<<gN, 256>>>(p_xcat, 48, w_emb, b_emb, nullptr, p_h, N, 1);
    gemm256<<<gN, 256>>>(p_h, 256, w_n2m, b_n2m, nullptr, p_m, N, 0);
    mprep_kernel<<<(N * 256 + 255) / 256, 256>>>(p_m, p_mh, p_ml, N * 256);
    edge_attr_kernel<<<gE64, 256>>>(dists, freq, w_r2m, b_r2m, p_eah, p_eal, E);
    cudaMemsetAsync(p_agg, 0, (size_t)N * 256 * sizeof(float));
    edge_mlp_hmma<<<gE64, 256, DSMEM>>>(p_mh, p_ml, p_eah, p_eal, edge_index, p_wt,
                                        mb1, mb2, mb3, mb4, p_agg, E);
    gemm256<<<gN, 256>>>(p_agg, 256, w_m2n, nullptr, p_h, p_t, N, 0);
    gemm256<<<gN, 256>>>(p_t, 256, fw1, fb1, nullptr, p_u, N, 1);
    gemm256<<<gN, 256>>>(p_u, 256, fw2, fb2, p_t, out, N, 0);
}

// round 5
// speedup vs baseline: 2.9691x; 1.5213x over previous
#include <cuda_runtime.h>
#include <cuda_bf16.h>
#include <math.h>
#include <stdint.h>

#define NN 10000
#define EE 160000
#define HH 256

// ---------------------------------------------------------------------------
// Scratch (no runtime allocation allowed)
// ---------------------------------------------------------------------------
__device__ float g_xcat[NN * 48];
__device__ float g_h[NN * HH];
__device__ float g_p[NN * HH];
__device__ float g_q[NN * HH];
__device__ float g_agg[NN * HH];
__device__ float g_t[NN * HH];
__device__ float g_u[NN * HH];
__device__ float g_wpa[256 * 256];
__device__ float g_wqb[256 * 256];
__device__ float g_wr2[32 * 256];
__device__ float g_cz[256];
// act1 (layer-1 activations) hi/lo bf16, [E, 256]
__device__ __nv_bfloat16 g_a1h[(size_t)EE * HH];
__device__ __nv_bfloat16 g_a1l[(size_t)EE * HH];
// Transposed weights W^T[N=256, K=256] K-major, per Kc=32 chunk.
// 24 tiles (L2: 0..7, L3: 8..15, L4: 16..23); tile = 8192 hi then 8192 lo bf16
__device__ __align__(16) __nv_bfloat16 g_wt[24 * 16384];

__device__ __forceinline__ float gelu_f(float x) {
    float x3 = x * x * x;
    return 0.5f * x * (1.0f + tanhf(0.7978845608028654f * (x + 0.044715f * x3)));
}
__device__ __forceinline__ float lrelu_f(float x) { return x > 0.0f ? x : 0.01f * x; }

// ---------------------------------------------------------------------------
// PTX helpers (sm_80-family: valid at .target sm_100)
// ---------------------------------------------------------------------------
__device__ __forceinline__ uint32_t smem_u32(const void* p) {
    uint32_t a;
    asm("{ .reg .u64 t; cvta.to.shared.u64 t, %1; cvt.u32.u64 %0, t; }" : "=r"(a) : "l"(p));
    return a;
}
__device__ __forceinline__ void cp_async16(uint32_t smem_addr, const void* gptr) {
    asm volatile("cp.async.cg.shared.global [%0], [%1], 16;\n" :: "r"(smem_addr), "l"(gptr));
}
#define CP_COMMIT() asm volatile("cp.async.commit_group;\n" ::: "memory")
#define CP_WAIT0()  asm volatile("cp.async.wait_group 0;\n" ::: "memory")
#define CP_WAIT1()  asm volatile("cp.async.wait_group 1;\n" ::: "memory")

__device__ __forceinline__ void ldsm4(uint32_t* f, uint32_t a) {
    asm volatile("ldmatrix.sync.aligned.m8n8.x4.shared.b16 {%0,%1,%2,%3}, [%4];\n"
                 : "=r"(f[0]), "=r"(f[1]), "=r"(f[2]), "=r"(f[3]) : "r"(a));
}
__device__ __forceinline__ void mma16816(float* d, const uint32_t* a, uint32_t b0, uint32_t b1) {
    asm volatile(
        "mma.sync.aligned.m16n8k16.row.col.f32.bf16.bf16.f32 "
        "{%0,%1,%2,%3}, {%4,%5,%6,%7}, {%8,%9}, {%0,%1,%2,%3};\n"
        : "+f"(d[0]), "+f"(d[1]), "+f"(d[2]), "+f"(d[3])
        : "r"(a[0]), "r"(a[1]), "r"(a[2]), "r"(a[3]), "r"(b0), "r"(b1));
}

// ---------------------------------------------------------------------------
// Node-side GEMM, BM=64, BN=128 (gridDim.y=2), BK=32
// C[rows,256] (half of cols per block) = act(A[rows,K] @ W[K,256] + bias) + res
// ---------------------------------------------------------------------------
__global__ __launch_bounds__(256, 2) void gemm_bn128(
    const float* __restrict__ A, int K, const float* __restrict__ W,
    const float* __restrict__ bias, const float* __restrict__ res,
    float* __restrict__ C, int rows, int act) {
    __shared__ float As[64 * 33];
    __shared__ float Bs[32 * 132];
    int tid = threadIdx.x, tx = tid & 15, ty = tid >> 4;
    int row0 = blockIdx.x * 64;
    int col0 = blockIdx.y * 128;
    float acc[4][8];
#pragma unroll
    for (int i = 0; i < 4; i++)
#pragma unroll
        for (int j = 0; j < 8; j++) acc[i][j] = 0.0f;
    for (int k0 = 0; k0 < K; k0 += 32) {
#pragma unroll
        for (int i = 0; i < 8; i++) {
            int idx = tid + i * 256, r = idx >> 5, c = idx & 31;
            int gr = row0 + r, gk = k0 + c;
            As[r * 33 + c] = (gr < rows && gk < K) ? A[(long)gr * K + gk] : 0.0f;
        }
#pragma unroll
        for (int i = 0; i < 16; i++) {
            int idx = tid + i * 256, r = idx >> 7, c = idx & 127;
            int gk = k0 + r;
            Bs[r * 132 + c] = (gk < K) ? W[(long)gk * 256 + col0 + c] : 0.0f;
        }
        __syncthreads();
#pragma unroll
        for (int kk = 0; kk < 32; kk++) {
            float a[4];
#pragma unroll
            for (int i = 0; i < 4; i++) a[i] = As[(ty * 4 + i) * 33 + kk];
#pragma unroll
            for (int j = 0; j < 8; j++) {
                float b = Bs[kk * 132 + tx + 16 * j];
#pragma unroll
                for (int i = 0; i < 4; i++) acc[i][j] = fmaf(a[i], b, acc[i][j]);
            }
        }
        __syncthreads();
    }
#pragma unroll
    for (int i = 0; i < 4; i++) {
        int r = row0 + ty * 4 + i;
        if (r < rows) {
#pragma unroll
            for (int j = 0; j < 8; j++) {
                int col = col0 + tx + 16 * j;
                float v = acc[i][j];
                if (bias) v += bias[col];
                if (act == 1) v = gelu_f(v);
                if (res) v += res[(long)r * 256 + col];
                C[(long)r * 256 + col] = v;
            }
        }
    }
}

// ---------------------------------------------------------------------------
// Small prep kernels
// ---------------------------------------------------------------------------
__global__ void xcat_kernel(const int* __restrict__ atom_types,
                            const float* __restrict__ x_extra,
                            const float* __restrict__ emb_table,
                            float* __restrict__ xcat, int N) {
    int idx = blockIdx.x * blockDim.x + threadIdx.x;
    if (idx < N * 48) {
        int n = idx / 48, c = idx - n * 48;
        xcat[idx] = (c < 32) ? emb_table[atom_types[n] * 32 + c] : x_extra[n * 16 + (c - 32)];
    }
}

// cz[n] = b_n2m @ (W1a + W1b) + b_r2m @ W1c + b1   (w1 = [768,256] row-major)
__global__ void cz_kernel(const float* __restrict__ b_n2m, const float* __restrict__ b_r2m,
                          const float* __restrict__ b1, const float* __restrict__ w1,
                          float* __restrict__ cz) {
    int n = threadIdx.x;
    float s = b1[n];
    for (int k = 0; k < 256; k++) {
        s += b_n2m[k] * (w1[k * 256 + n] + w1[(256 + k) * 256 + n]);
        s += b_r2m[k] * w1[(512 + k) * 256 + n];
    }
    cz[n] = s;
}

// mlp_w2/3/4 -> W^T hi/lo chunk tiles (24 tiles)
__global__ void wprep_kernel(const float* __restrict__ w2, const float* __restrict__ w3,
                             const float* __restrict__ w4, __nv_bfloat16* __restrict__ wt) {
    int id = blockIdx.x * blockDim.x + threadIdx.x;
    if (id >= 768 * 256) return;
    int kg = id >> 8, n = id & 255;
    const float* w;
    int kl, t;
    if (kg < 256)      { w = w2; kl = kg;       t = kl >> 5; }
    else if (kg < 512) { w = w3; kl = kg - 256; t = 8 + (kl >> 5); }
    else               { w = w4; kl = kg - 512; t = 16 + (kl >> 5); }
    int kk = kl & 31;
    float v = w[(long)kl * 256 + n];
    __nv_bfloat16 h = __float2bfloat16(v);
    __nv_bfloat16 l = __float2bfloat16(v - __bfloat162float(h));
    size_t base = (size_t)t * 16384 + n * 32 + kk;
    wt[base] = h;
    wt[base + 8192] = l;
}

// ---------------------------------------------------------------------------
// edge combine: act1 = lrelu( rbf@Wr2 + p[src] + q[dst] + cz ) -> bf16 hi/lo
// ---------------------------------------------------------------------------
__global__ __launch_bounds__(256, 2) void edge_combine(
    const float* __restrict__ dists, const float* __restrict__ freq,
    const float* __restrict__ wr2, const float* __restrict__ p,
    const float* __restrict__ q, const float* __restrict__ cz,
    const int* __restrict__ edge_index,
    __nv_bfloat16* __restrict__ a1h, __nv_bfloat16* __restrict__ a1l, int E) {
    __shared__ float Rs[64 * 33];
    __shared__ float Bs[32 * 256];
    __shared__ float s_freq[32];
    __shared__ float s_cz[256];
    __shared__ int s_src[64], s_dst[64];
    int tid = threadIdx.x, tx = tid & 15, ty = tid >> 4;
    int e0 = blockIdx.x * 64;
    if (tid < 32) s_freq[tid] = freq[tid];
    s_cz[tid] = cz[tid];
    if (tid < 64) {
        int e = e0 + tid;
        s_src[tid] = (e < E) ? edge_index[e] : 0;
        s_dst[tid] = (e < E) ? edge_index[E + e] : 0;
    }
#pragma unroll
    for (int i = 0; i < 32; i++) Bs[i * 256 + tid] = wr2[i * 256 + tid];
    __syncthreads();
#pragma unroll
    for (int i = 0; i < 8; i++) {
        int idx = tid + i * 256, el = idx >> 5, r = idx & 31;
        int e = e0 + el;
        float d = (e < E) ? dists[e] * 0.2f : 1.0f;
        float d2 = d * d, d5 = d2 * d2 * d;
        float env = 1.0f / d + d5 * (-28.0f + d * (48.0f + d * (-21.0f)));
        Rs[el * 33 + r] = env * sinf(s_freq[r] * d);
    }
    __syncthreads();
    float acc[4][16];
#pragma unroll
    for (int i = 0; i < 4; i++)
#pragma unroll
        for (int j = 0; j < 16; j++) acc[i][j] = 0.0f;
#pragma unroll
    for (int kk = 0; kk < 32; kk++) {
        float a[4];
#pragma unroll
        for (int i = 0; i < 4; i++) a[i] = Rs[(ty * 4 + i) * 33 + kk];
#pragma unroll
        for (int j = 0; j < 16; j++) {
            float b = Bs[kk * 256 + tx + 16 * j];
#pragma unroll
            for (int i = 0; i < 4; i++) acc[i][j] = fmaf(a[i], b, acc[i][j]);
        }
    }
#pragma unroll
    for (int i = 0; i < 4; i++) {
        int r = ty * 4 + i;
        int e = e0 + r;
        if (e < E) {
            const float* prow = p + (size_t)s_src[r] * 256;
            const float* qrow = q + (size_t)s_dst[r] * 256;
#pragma unroll
            for (int j = 0; j < 16; j++) {
                int col = tx + 16 * j;
                float v = acc[i][j] + prow[col] + qrow[col] + s_cz[col];
                v = lrelu_f(v);
                __nv_bfloat16 h = __float2bfloat16(v);
                a1h[(size_t)e * 256 + col] = h;
                a1l[(size_t)e * 256 + col] = __float2bfloat16(v - __bfloat162float(h));
            }
        }
    }
}

// ---------------------------------------------------------------------------
// HMMA fused edge MLP (layers 2..4 only). CTA = 64 edges x 256 outputs, 8 warps,
// warp tile 32x64, mma.sync m16n8k16 bf16 hi/lo (3 products), fp32 acc.
// Dynamic SMEM:
//   ACT_HI [0,     33792) : 64 rows x 264 bf16 (stride 528B)
//   ACT_LO [33792, 67584)
//   BBUF   [67584, 149504): 2 x (hi 256x40 bf16 stride 80B | lo +20480)
// ---------------------------------------------------------------------------
#define ACT_HI 0
#define ACT_LO 33792
#define BBUF   67584
#define DSMEM  149504

__global__ __launch_bounds__(256) void edge_mlp_hmma(
    const __nv_bfloat16* __restrict__ a1h, const __nv_bfloat16* __restrict__ a1l,
    const int* __restrict__ edge_index, const __nv_bfloat16* __restrict__ wt,
    const float* __restrict__ b2, const float* __restrict__ b3,
    const float* __restrict__ b4, float* __restrict__ agg, int E) {
    extern __shared__ __align__(16) char dsm[];
    __shared__ int s_dst[64];
    __shared__ float s_bias[768];

    const int tid = threadIdx.x;
    const int wid = tid >> 5, lane = tid & 31;
    const int wm = wid >> 2, wn = wid & 3;
    const int r0 = wm * 32;
    const int c0 = wn * 64;
    const int e0 = blockIdx.x * 64;
    const uint32_t sb = smem_u32(dsm);

    for (int i = tid; i < 768; i += 256) {
        const float* b = (i < 256) ? b2 : (i < 512) ? b3 : b4;
        s_bias[i] = b[i & 255];
    }
    if (tid < 64) {
        int e = e0 + tid;
        s_dst[tid] = (e < E) ? edge_index[E + e] : 0;
    }

    float acc[2][8][4];
#pragma unroll
    for (int mt = 0; mt < 2; mt++)
#pragma unroll
        for (int nt = 0; nt < 8; nt++)
#pragma unroll
            for (int i = 0; i < 4; i++) acc[mt][nt][i] = 0.0f;

    auto prefetchB = [&](int t, int buf) {
        const char* wsrc = (const char*)wt + (size_t)t * 32768;
        uint32_t dbase = sb + BBUF + buf * 40960;
#pragma unroll
        for (int it = 0; it < 8; it++) {
            int id = tid + it * 256;
            int n = id & 255, rest = id >> 8;
            int seg = rest & 3, hl = rest >> 2;
            cp_async16(dbase + hl * 20480 + n * 80 + seg * 16,
                       wsrc + hl * 16384 + n * 64 + seg * 16);
        }
    };
    auto loadACT = [&]() {
#pragma unroll
        for (int it = 0; it < 16; it++) {
            int id = tid + it * 256;
            int seg = id & 31;
            int hl = (id >> 5) & 1;
            int row = id >> 6;
            int e = e0 + row;
            if (e >= E) e = E - 1;
            const char* sp = (const char*)(hl ? a1l : a1h) + (size_t)e * 512 + seg * 16;
            cp_async16(sb + (hl ? ACT_LO : ACT_HI) + (uint32_t)row * 528 + seg * 16, sp);
        }
    };
    auto compute = [&](uint32_t abase, uint32_t bbase) {
#pragma unroll
        for (int s = 0; s < 2; s++) {
            int ko2 = s * 32;
            uint32_t ah[2][4], al[2][4];
#pragma unroll
            for (int mt = 0; mt < 2; mt++) {
                uint32_t ad = abase + (uint32_t)(r0 + mt * 16 + (lane & 15)) * 528 +
                              ko2 + ((lane >> 4) << 4);
                ldsm4(ah[mt], ad);
                ldsm4(al[mt], ad + (ACT_LO - ACT_HI));
            }
            uint32_t bh[4][4], bl[4][4];
#pragma unroll
            for (int q = 0; q < 4; q++) {
                int n = c0 + q * 16 + (lane & 7) + ((lane & 16) >> 1);
                uint32_t bd = bbase + (uint32_t)n * 80 + ko2 + ((lane & 8) << 1);
                ldsm4(bh[q], bd);
                ldsm4(bl[q], bd + 20480);
            }
#pragma unroll
            for (int mt = 0; mt < 2; mt++)
#pragma unroll
                for (int nt = 0; nt < 8; nt++)
                    mma16816(acc[mt][nt], ah[mt], bh[nt >> 1][(nt & 1) * 2], bh[nt >> 1][(nt & 1) * 2 + 1]);
#pragma unroll
            for (int mt = 0; mt < 2; mt++)
#pragma unroll
                for (int nt = 0; nt < 8; nt++)
                    mma16816(acc[mt][nt], al[mt], bh[nt >> 1][(nt & 1) * 2], bh[nt >> 1][(nt & 1) * 2 + 1]);
#pragma unroll
            for (int mt = 0; mt < 2; mt++)
#pragma unroll
                for (int nt = 0; nt < 8; nt++)
                    mma16816(acc[mt][nt], ah[mt], bl[nt >> 1][(nt & 1) * 2], bl[nt >> 1][(nt & 1) * 2 + 1]);
        }
    };
    auto epilogue_act = [&](int bidx) {
#pragma unroll
        for (int mt = 0; mt < 2; mt++) {
#pragma unroll
            for (int nt = 0; nt < 8; nt++) {
                int ra = r0 + mt * 16 + (lane >> 2);
                int ca = c0 + nt * 8 + 2 * (lane & 3);
                float bv0 = s_bias[bidx * 256 + ca], bv1 = s_bias[bidx * 256 + ca + 1];
#pragma unroll
                for (int half = 0; half < 2; half++) {
                    int r = ra + half * 8;
                    float v0 = lrelu_f(acc[mt][nt][half * 2 + 0] + bv0);
                    float v1 = lrelu_f(acc[mt][nt][half * 2 + 1] + bv1);
                    __nv_bfloat16 h0 = __float2bfloat16(v0);
                    __nv_bfloat16 h1 = __float2bfloat16(v1);
                    __nv_bfloat162 hp; hp.x = h0; hp.y = h1;
                    __nv_bfloat162 lp;
                    lp.x = __float2bfloat16(v0 - __bfloat162float(h0));
                    lp.y = __float2bfloat16(v1 - __bfloat162float(h1));
                    uint32_t off = (uint32_t)r * 528 + (uint32_t)ca * 2;
                    *(__nv_bfloat162*)(dsm + ACT_HI + off) = hp;
                    *(__nv_bfloat162*)(dsm + ACT_LO + off) = lp;
                    acc[mt][nt][half * 2 + 0] = 0.0f;
                    acc[mt][nt][half * 2 + 1] = 0.0f;
                }
            }
        }
    };

    // pipeline prime: group0 = ACT + B(0), group1 = B(1)
    loadACT();
    prefetchB(0, 0);
    CP_COMMIT();
    prefetchB(1, 1);
    CP_COMMIT();

    // 24 chunks: g = L*8 + c, L in {0(W2),1(W3),2(W4)}
    for (int g = 0; g < 24; g++) {
        if (g < 23) { CP_WAIT1(); } else { CP_WAIT0(); }
        __syncthreads();
        compute(sb + ACT_HI + (uint32_t)(g & 7) * 64, sb + BBUF + (g & 1) * 40960);
        __syncthreads();
        if (g + 2 < 24) {
            prefetchB(g + 2, g & 1);
            CP_COMMIT();
        }
        if ((g & 7) == 7) {
            int L = g >> 3;
            if (L < 2) {
                epilogue_act(L);
                __syncthreads();
            } else {
                // final: bias + scatter-add
#pragma unroll
                for (int mt = 0; mt < 2; mt++) {
#pragma unroll
                    for (int nt = 0; nt < 8; nt++) {
                        int ra = r0 + mt * 16 + (lane >> 2);
                        int ca = c0 + nt * 8 + 2 * (lane & 3);
                        float bv0 = s_bias[512 + ca], bv1 = s_bias[512 + ca + 1];
#pragma unroll
                        for (int half = 0; half < 2; half++) {
                            int r = ra + half * 8;
                            int e = e0 + r;
                            if (e < E) {
                                int dn = s_dst[r];
                                atomicAdd(&agg[(size_t)dn * 256 + ca], acc[mt][nt][half * 2 + 0] + bv0);
                                atomicAdd(&agg[(size_t)dn * 256 + ca + 1], acc[mt][nt][half * 2 + 1] + bv1);
                            }
                        }
                    }
                }
            }
        }
    }
}

// ---------------------------------------------------------------------------
extern "C" void kernel_launch(void* const* d_in, const int* in_sizes, int n_in,
                              void* d_out, int out_size) {
    const int* atom_types = (const int*)d_in[0];
    const float* x_extra = (const float*)d_in[1];
    const int* edge_index = (const int*)d_in[2];
    const float* dists = (const float*)d_in[3];
    const float* freq = (const float*)d_in[4];
    const float* emb_table = (const float*)d_in[5];
    const float* w_emb = (const float*)d_in[6];
    const float* b_emb = (const float*)d_in[7];
    const float* w_n2m = (const float*)d_in[8];
    const float* b_n2m = (const float*)d_in[9];
    const float* w_r2m = (const float*)d_in[10];
    const float* b_r2m = (const float*)d_in[11];
    const float* w_m2n = (const float*)d_in[12];
    const float* mw1 = (const float*)d_in[13];
    const float* mb1 = (const float*)d_in[14];
    const float* mw2 = (const float*)d_in[15];
    const float* mb2 = (const float*)d_in[16];
    const float* mw3 = (const float*)d_in[17];
    const float* mb3 = (const float*)d_in[18];
    const float* mw4 = (const float*)d_in[19];
    const float* mb4 = (const float*)d_in[20];
    const float* fw1 = (const float*)d_in[21];
    const float* fb1 = (const float*)d_in[22];
    const float* fw2 = (const float*)d_in[23];
    const float* fb2 = (const float*)d_in[24];
    float* out = (float*)d_out;

    int N = in_sizes[0];
    int E = in_sizes[2] / 2;

    float *p_xcat, *p_h, *p_p, *p_q, *p_agg, *p_t, *p_u;
    float *p_wpa, *p_wqb, *p_wr2, *p_cz;
    __nv_bfloat16 *p_a1h, *p_a1l, *p_wt;
    cudaGetSymbolAddress((void**)&p_xcat, g_xcat);
    cudaGetSymbolAddress((void**)&p_h, g_h);
    cudaGetSymbolAddress((void**)&p_p, g_p);
    cudaGetSymbolAddress((void**)&p_q, g_q);
    cudaGetSymbolAddress((void**)&p_agg, g_agg);
    cudaGetSymbolAddress((void**)&p_t, g_t);
    cudaGetSymbolAddress((void**)&p_u, g_u);
    cudaGetSymbolAddress((void**)&p_wpa, g_wpa);
    cudaGetSymbolAddress((void**)&p_wqb, g_wqb);
    cudaGetSymbolAddress((void**)&p_wr2, g_wr2);
    cudaGetSymbolAddress((void**)&p_cz, g_cz);
    cudaGetSymbolAddress((void**)&p_a1h, g_a1h);
    cudaGetSymbolAddress((void**)&p_a1l, g_a1l);
    cudaGetSymbolAddress((void**)&p_wt, g_wt);

    cudaFuncSetAttribute(edge_mlp_hmma, cudaFuncAttributeMaxDynamicSharedMemorySize, DSMEM);

    dim3 gN((N + 63) / 64, 2);
    dim3 g256(4, 2), g32(1, 2);
    int gE64 = (E + 63) / 64;

    // weight folding preps
    gemm_bn128<<<g256, 256>>>(w_n2m, 256, mw1, nullptr, nullptr, p_wpa, 256, 0);
    gemm_bn128<<<g256, 256>>>(w_n2m, 256, mw1 + 256 * 256, nullptr, nullptr, p_wqb, 256, 0);
    gemm_bn128<<<g32, 256>>>(w_r2m, 256, mw1 + 512 * 256, nullptr, nullptr, p_wr2, 32, 0);
    cz_kernel<<<1, 256>>>(b_n2m, b_r2m, mb1, mw1, p_cz);
    wprep_kernel<<<768, 256>>>(mw2, mw3, mw4, p_wt);

    // node pipeline
    xcat_kernel<<<(N * 48 + 255) / 256, 256>>>(atom_types, x_extra, emb_table, p_xcat, N);
    gemm_bn128<<<gN, 256>>>(p_xcat, 48, w_emb, b_emb, nullptr, p_h, N, 1);
    gemm_bn128<<<gN, 256>>>(p_h, 256, p_wpa, nullptr, nullptr, p_p, N, 0);
    gemm_bn128<<<gN, 256>>>(p_h, 256, p_wqb, nullptr, nullptr, p_q, N, 0);

    // edge pipeline
    edge_combine<<<gE64, 256>>>(dists, freq, p_wr2, p_p, p_q, p_cz, edge_index,
                                p_a1h, p_a1l, E);
    cudaMemsetAsync(p_agg, 0, (size_t)N * 256 * sizeof(float));
    edge_mlp_hmma<<<gE64, 256, DSMEM>>>(p_a1h, p_a1l, edge_index, p_wt,
                                        mb2, mb3, mb4, p_agg, E);

    // output
    gemm_bn128<<<gN, 256>>>(p_agg, 256, w_m2n, nullptr, p_h, p_t, N, 0);
    gemm_bn128<<<gN, 256>>>(p_t, 256, fw1, fb1, nullptr, p_u, N, 1);
    gemm_bn128<<<gN, 256>>>(p_u, 256, fw2, fb2, p_t, out, N, 0);
}

// round 6
// speedup vs baseline: 3.1119x; 1.0481x over previous
#include <cuda_runtime.h>
#include <cuda_bf16.h>
#include <math.h>
#include <stdint.h>

#define NN 10000
#define EE 160000
#define HH 256

// ---------------------------------------------------------------------------
// Scratch (no runtime allocation allowed)
// ---------------------------------------------------------------------------
__device__ float g_xcat[NN * 48];
__device__ float g_h[NN * HH];
__device__ float g_p[NN * HH];
__device__ float g_q[NN * HH];
__device__ float g_agg[NN * HH];
__device__ float g_t[NN * HH];
__device__ float g_u[NN * HH];
__device__ float g_wpa[256 * 256];
__device__ float g_wqb[256 * 256];
__device__ float g_wr2[32 * 256];
__device__ float g_cz[256];
// act1 (layer-1 activations) hi/lo bf16, [E, 256]
__device__ __nv_bfloat16 g_a1h[(size_t)EE * HH];
__device__ __nv_bfloat16 g_a1l[(size_t)EE * HH];
// Transposed weights W^T[N=256, K=256] K-major, per Kc=32 chunk.
// 24 tiles (L2: 0..7, L3: 8..15, L4: 16..23); tile = 8192 hi then 8192 lo bf16
__device__ __align__(16) __nv_bfloat16 g_wt[24 * 16384];

__device__ __forceinline__ float gelu_f(float x) {
    float x3 = x * x * x;
    return 0.5f * x * (1.0f + tanhf(0.7978845608028654f * (x + 0.044715f * x3)));
}
__device__ __forceinline__ float lrelu_f(float x) { return x > 0.0f ? x : 0.01f * x; }

// ---------------------------------------------------------------------------
// PTX helpers (sm_80/sm_90 base ISA: valid at .target sm_100)
// ---------------------------------------------------------------------------
__device__ __forceinline__ uint32_t smem_u32(const void* p) {
    uint32_t a;
    asm("{ .reg .u64 t; cvta.to.shared.u64 t, %1; cvt.u32.u64 %0, t; }" : "=r"(a) : "l"(p));
    return a;
}
__device__ __forceinline__ void cp_async16(uint32_t smem_addr, const void* gptr) {
    asm volatile("cp.async.cg.shared.global [%0], [%1], 16;\n" :: "r"(smem_addr), "l"(gptr));
}
#define CP_COMMIT() asm volatile("cp.async.commit_group;\n" ::: "memory")
#define CP_WAIT0()  asm volatile("cp.async.wait_group 0;\n" ::: "memory")
#define CP_WAIT1()  asm volatile("cp.async.wait_group 1;\n" ::: "memory")

// SMEM -> GMEM bulk reduction (sm_90 base ISA)
__device__ __forceinline__ void bulk_reduce_add_f32(void* gdst, uint32_t ssrc, uint32_t bytes) {
    asm volatile("cp.reduce.async.bulk.global.shared::cta.bulk_group.add.f32 [%0], [%1], %2;\n"
                 :: "l"(gdst), "r"(ssrc), "r"(bytes) : "memory");
}
#define BULK_COMMIT() asm volatile("cp.async.bulk.commit_group;" ::: "memory")
#define BULK_WAIT0()  asm volatile("cp.async.bulk.wait_group 0;" ::: "memory")
#define FENCE_ASYNC() asm volatile("fence.proxy.async.shared::cta;" ::: "memory")

__device__ __forceinline__ void ldsm4(uint32_t* f, uint32_t a) {
    asm volatile("ldmatrix.sync.aligned.m8n8.x4.shared.b16 {%0,%1,%2,%3}, [%4];\n"
                 : "=r"(f[0]), "=r"(f[1]), "=r"(f[2]), "=r"(f[3]) : "r"(a));
}
__device__ __forceinline__ void mma16816(float* d, const uint32_t* a, uint32_t b0, uint32_t b1) {
    asm volatile(
        "mma.sync.aligned.m16n8k16.row.col.f32.bf16.bf16.f32 "
        "{%0,%1,%2,%3}, {%4,%5,%6,%7}, {%8,%9}, {%0,%1,%2,%3};\n"
        : "+f"(d[0]), "+f"(d[1]), "+f"(d[2]), "+f"(d[3])
        : "r"(a[0]), "r"(a[1]), "r"(a[2]), "r"(a[3]), "r"(b0), "r"(b1));
}

// ---------------------------------------------------------------------------
// Node-side GEMM, BM=64, BN=128 (gridDim.y=2), BK=32; optional second (W,C)
// pair selected by blockIdx.z (for fused wpa/wqb prep).
// ---------------------------------------------------------------------------
__global__ __launch_bounds__(256, 2) void gemm_bn128(
    const float* __restrict__ A, int K, const float* __restrict__ W,
    const float* __restrict__ bias, const float* __restrict__ res,
    float* __restrict__ C, int rows, int act,
    const float* __restrict__ W2, float* __restrict__ C2) {
    __shared__ float As[64 * 33];
    __shared__ float Bs[32 * 132];
    if (blockIdx.z == 1) { W = W2; C = C2; }
    int tid = threadIdx.x, tx = tid & 15, ty = tid >> 4;
    int row0 = blockIdx.x * 64;
    int col0 = blockIdx.y * 128;
    float acc[4][8];
#pragma unroll
    for (int i = 0; i < 4; i++)
#pragma unroll
        for (int j = 0; j < 8; j++) acc[i][j] = 0.0f;
    for (int k0 = 0; k0 < K; k0 += 32) {
#pragma unroll
        for (int i = 0; i < 8; i++) {
            int idx = tid + i * 256, r = idx >> 5, c = idx & 31;
            int gr = row0 + r, gk = k0 + c;
            As[r * 33 + c] = (gr < rows && gk < K) ? A[(long)gr * K + gk] : 0.0f;
        }
#pragma unroll
        for (int i = 0; i < 16; i++) {
            int idx = tid + i * 256, r = idx >> 7, c = idx & 127;
            int gk = k0 + r;
            Bs[r * 132 + c] = (gk < K) ? W[(long)gk * 256 + col0 + c] : 0.0f;
        }
        __syncthreads();
#pragma unroll
        for (int kk = 0; kk < 32; kk++) {
            float a[4];
#pragma unroll
            for (int i = 0; i < 4; i++) a[i] = As[(ty * 4 + i) * 33 + kk];
#pragma unroll
            for (int j = 0; j < 8; j++) {
                float b = Bs[kk * 132 + tx + 16 * j];
#pragma unroll
                for (int i = 0; i < 4; i++) acc[i][j] = fmaf(a[i], b, acc[i][j]);
            }
        }
        __syncthreads();
    }
#pragma unroll
    for (int i = 0; i < 4; i++) {
        int r = row0 + ty * 4 + i;
        if (r < rows) {
#pragma unroll
            for (int j = 0; j < 8; j++) {
                int col = col0 + tx + 16 * j;
                float v = acc[i][j];
                if (bias) v += bias[col];
                if (act == 1) v = gelu_f(v);
                if (res) v += res[(long)r * 256 + col];
                C[(long)r * 256 + col] = v;
            }
        }
    }
}

// ---------------------------------------------------------------------------
// Small prep kernels
// ---------------------------------------------------------------------------
__global__ void xcat_kernel(const int* __restrict__ atom_types,
                            const float* __restrict__ x_extra,
                            const float* __restrict__ emb_table,
                            float* __restrict__ xcat, int N) {
    int idx = blockIdx.x * blockDim.x + threadIdx.x;
    if (idx < N * 48) {
        int n = idx / 48, c = idx - n * 48;
        xcat[idx] = (c < 32) ? emb_table[atom_types[n] * 32 + c] : x_extra[n * 16 + (c - 32)];
    }
}

// cz[n] = b_n2m @ (W1a + W1b) + b_r2m @ W1c + b1  -- one block per n, parallel-k
__global__ void cz_kernel(const float* __restrict__ b_n2m, const float* __restrict__ b_r2m,
                          const float* __restrict__ b1, const float* __restrict__ w1,
                          float* __restrict__ cz) {
    __shared__ float red[256];
    int n = blockIdx.x, k = threadIdx.x;
    float s = b_n2m[k] * (w1[k * 256 + n] + w1[(256 + k) * 256 + n]) +
              b_r2m[k & 255] * 0.0f;  // placeholder to keep shape; real term below
    // b_r2m has 256 entries; W1c rows are k=0..255 as well
    s += b_r2m[k] * w1[(512 + k) * 256 + n];
    red[k] = s;
    __syncthreads();
    for (int st = 128; st > 0; st >>= 1) {
        if (k < st) red[k] += red[k + st];
        __syncthreads();
    }
    if (k == 0) cz[n] = red[0] + b1[n];
}

// mlp_w2/3/4 -> W^T hi/lo chunk tiles (24 tiles)
__global__ void wprep_kernel(const float* __restrict__ w2, const float* __restrict__ w3,
                             const float* __restrict__ w4, __nv_bfloat16* __restrict__ wt) {
    int id = blockIdx.x * blockDim.x + threadIdx.x;
    if (id >= 768 * 256) return;
    int kg = id >> 8, n = id & 255;
    const float* w;
    int kl, t;
    if (kg < 256)      { w = w2; kl = kg;       t = kl >> 5; }
    else if (kg < 512) { w = w3; kl = kg - 256; t = 8 + (kl >> 5); }
    else               { w = w4; kl = kg - 512; t = 16 + (kl >> 5); }
    int kk = kl & 31;
    float v = w[(long)kl * 256 + n];
    __nv_bfloat16 h = __float2bfloat16(v);
    __nv_bfloat16 l = __float2bfloat16(v - __bfloat162float(h));
    size_t base = (size_t)t * 16384 + n * 32 + kk;
    wt[base] = h;
    wt[base + 8192] = l;
}

// ---------------------------------------------------------------------------
// edge combine: act1 = lrelu( rbf@Wr2 + p[src] + q[dst] + cz ) -> bf16 hi/lo
// ---------------------------------------------------------------------------
__global__ __launch_bounds__(256, 2) void edge_combine(
    const float* __restrict__ dists, const float* __restrict__ freq,
    const float* __restrict__ wr2, const float* __restrict__ p,
    const float* __restrict__ q, const float* __restrict__ cz,
    const int* __restrict__ edge_index,
    __nv_bfloat16* __restrict__ a1h, __nv_bfloat16* __restrict__ a1l, int E) {
    __shared__ float Rs[64 * 33];
    __shared__ float Bs[32 * 256];
    __shared__ float s_freq[32];
    __shared__ float s_cz[256];
    __shared__ int s_src[64], s_dst[64];
    int tid = threadIdx.x, tx = tid & 15, ty = tid >> 4;
    int e0 = blockIdx.x * 64;
    if (tid < 32) s_freq[tid] = freq[tid];
    s_cz[tid] = cz[tid];
    if (tid < 64) {
        int e = e0 + tid;
        s_src[tid] = (e < E) ? edge_index[e] : 0;
        s_dst[tid] = (e < E) ? edge_index[E + e] : 0;
    }
#pragma unroll
    for (int i = 0; i < 32; i++) Bs[i * 256 + tid] = wr2[i * 256 + tid];
    __syncthreads();
#pragma unroll
    for (int i = 0; i < 8; i++) {
        int idx = tid + i * 256, el = idx >> 5, r = idx & 31;
        int e = e0 + el;
        float d = (e < E) ? dists[e] * 0.2f : 1.0f;
        float d2 = d * d, d5 = d2 * d2 * d;
        float env = 1.0f / d + d5 * (-28.0f + d * (48.0f + d * (-21.0f)));
        Rs[el * 33 + r] = env * sinf(s_freq[r] * d);
    }
    __syncthreads();
    float acc[4][16];
#pragma unroll
    for (int i = 0; i < 4; i++)
#pragma unroll
        for (int j = 0; j < 16; j++) acc[i][j] = 0.0f;
#pragma unroll
    for (int kk = 0; kk < 32; kk++) {
        float a[4];
#pragma unroll
        for (int i = 0; i < 4; i++) a[i] = Rs[(ty * 4 + i) * 33 + kk];
#pragma unroll
        for (int j = 0; j < 16; j++) {
            float b = Bs[kk * 256 + tx + 16 * j];
#pragma unroll
            for (int i = 0; i < 4; i++) acc[i][j] = fmaf(a[i], b, acc[i][j]);
        }
    }
#pragma unroll
    for (int i = 0; i < 4; i++) {
        int r = ty * 4 + i;
        int e = e0 + r;
        if (e < E) {
            const float* prow = p + (size_t)s_src[r] * 256;
            const float* qrow = q + (size_t)s_dst[r] * 256;
#pragma unroll
            for (int j = 0; j < 16; j++) {
                int col = tx + 16 * j;
                float v = acc[i][j] + prow[col] + qrow[col] + s_cz[col];
                v = lrelu_f(v);
                __nv_bfloat16 h = __float2bfloat16(v);
                a1h[(size_t)e * 256 + col] = h;
                a1l[(size_t)e * 256 + col] = __float2bfloat16(v - __bfloat162float(h));
            }
        }
    }
}

// ---------------------------------------------------------------------------
// HMMA fused edge MLP (layers 2..4). CTA = 64 edges x 256 outputs, 8 warps,
// 3-deep B ring (prefetch distance 2), ONE sync per chunk.
// Final layer: fp32 rows assembled in SMEM, scattered via cp.reduce.async.bulk.
// Dynamic SMEM:
//   ACT_HI [0,     33792) : 64 rows x 264 bf16 (stride 528B)   (also FOUT fp32)
//   ACT_LO [33792, 67584)
//   BBUF   [67584, 190464): 3 x (hi 256x40 bf16 stride 80B | lo +20480)
// ---------------------------------------------------------------------------
#define ACT_HI 0
#define ACT_LO 33792
#define BBUF   67584
#define DSMEM  190464

__global__ __launch_bounds__(256) void edge_mlp_hmma(
    const __nv_bfloat16* __restrict__ a1h, const __nv_bfloat16* __restrict__ a1l,
    const int* __restrict__ edge_index, const __nv_bfloat16* __restrict__ wt,
    const float* __restrict__ b2, const float* __restrict__ b3,
    const float* __restrict__ b4, float* __restrict__ agg, int E) {
    extern __shared__ __align__(16) char dsm[];
    __shared__ int s_dst[64];
    __shared__ float s_bias[768];

    const int tid = threadIdx.x;
    const int wid = tid >> 5, lane = tid & 31;
    const int wm = wid >> 2, wn = wid & 3;
    const int r0 = wm * 32;
    const int c0 = wn * 64;
    const int e0 = blockIdx.x * 64;
    const uint32_t sb = smem_u32(dsm);

    for (int i = tid; i < 768; i += 256) {
        const float* b = (i < 256) ? b2 : (i < 512) ? b3 : b4;
        s_bias[i] = b[i & 255];
    }
    if (tid < 64) {
        int e = e0 + tid;
        s_dst[tid] = (e < E) ? edge_index[E + e] : 0;
    }

    float acc[2][8][4];
#pragma unroll
    for (int mt = 0; mt < 2; mt++)
#pragma unroll
        for (int nt = 0; nt < 8; nt++)
#pragma unroll
            for (int i = 0; i < 4; i++) acc[mt][nt][i] = 0.0f;

    auto prefetchB = [&](int t, int buf) {
        const char* wsrc = (const char*)wt + (size_t)t * 32768;
        uint32_t dbase = sb + BBUF + buf * 40960;
#pragma unroll
        for (int it = 0; it < 8; it++) {
            int id = tid + it * 256;
            int n = id & 255, rest = id >> 8;
            int seg = rest & 3, hl = rest >> 2;
            cp_async16(dbase + hl * 20480 + n * 80 + seg * 16,
                       wsrc + hl * 16384 + n * 64 + seg * 16);
        }
    };
    auto loadACT = [&]() {
#pragma unroll
        for (int it = 0; it < 16; it++) {
            int id = tid + it * 256;
            int seg = id & 31;
            int hl = (id >> 5) & 1;
            int row = id >> 6;
            int e = e0 + row;
            if (e >= E) e = E - 1;
            const char* sp = (const char*)(hl ? a1l : a1h) + (size_t)e * 512 + seg * 16;
            cp_async16(sb + (hl ? ACT_LO : ACT_HI) + (uint32_t)row * 528 + seg * 16, sp);
        }
    };
    auto compute = [&](uint32_t abase, uint32_t bbase) {
#pragma unroll
        for (int s = 0; s < 2; s++) {
            int ko2 = s * 32;
            uint32_t ah[2][4], al[2][4];
#pragma unroll
            for (int mt = 0; mt < 2; mt++) {
                uint32_t ad = abase + (uint32_t)(r0 + mt * 16 + (lane & 15)) * 528 +
                              ko2 + ((lane >> 4) << 4);
                ldsm4(ah[mt], ad);
                ldsm4(al[mt], ad + (ACT_LO - ACT_HI));
            }
            uint32_t bh[4][4], bl[4][4];
#pragma unroll
            for (int q = 0; q < 4; q++) {
                int n = c0 + q * 16 + (lane & 7) + ((lane & 16) >> 1);
                uint32_t bd = bbase + (uint32_t)n * 80 + ko2 + ((lane & 8) << 1);
                ldsm4(bh[q], bd);
                ldsm4(bl[q], bd + 20480);
            }
#pragma unroll
            for (int mt = 0; mt < 2; mt++)
#pragma unroll
                for (int nt = 0; nt < 8; nt++)
                    mma16816(acc[mt][nt], ah[mt], bh[nt >> 1][(nt & 1) * 2], bh[nt >> 1][(nt & 1) * 2 + 1]);
#pragma unroll
            for (int mt = 0; mt < 2; mt++)
#pragma unroll
                for (int nt = 0; nt < 8; nt++)
                    mma16816(acc[mt][nt], al[mt], bh[nt >> 1][(nt & 1) * 2], bh[nt >> 1][(nt & 1) * 2 + 1]);
#pragma unroll
            for (int mt = 0; mt < 2; mt++)
#pragma unroll
                for (int nt = 0; nt < 8; nt++)
                    mma16816(acc[mt][nt], ah[mt], bl[nt >> 1][(nt & 1) * 2], bl[nt >> 1][(nt & 1) * 2 + 1]);
        }
    };
    auto epilogue_act = [&](int bidx) {
#pragma unroll
        for (int mt = 0; mt < 2; mt++) {
#pragma unroll
            for (int nt = 0; nt < 8; nt++) {
                int ra = r0 + mt * 16 + (lane >> 2);
                int ca = c0 + nt * 8 + 2 * (lane & 3);
                float bv0 = s_bias[bidx * 256 + ca], bv1 = s_bias[bidx * 256 + ca + 1];
#pragma unroll
                for (int half = 0; half < 2; half++) {
                    int r = ra + half * 8;
                    float v0 = lrelu_f(acc[mt][nt][half * 2 + 0] + bv0);
                    float v1 = lrelu_f(acc[mt][nt][half * 2 + 1] + bv1);
                    __nv_bfloat16 h0 = __float2bfloat16(v0);
                    __nv_bfloat16 h1 = __float2bfloat16(v1);
                    __nv_bfloat162 hp; hp.x = h0; hp.y = h1;
                    __nv_bfloat162 lp;
                    lp.x = __float2bfloat16(v0 - __bfloat162float(h0));
                    lp.y = __float2bfloat16(v1 - __bfloat162float(h1));
                    uint32_t off = (uint32_t)r * 528 + (uint32_t)ca * 2;
                    *(__nv_bfloat162*)(dsm + ACT_HI + off) = hp;
                    *(__nv_bfloat162*)(dsm + ACT_LO + off) = lp;
                    acc[mt][nt][half * 2 + 0] = 0.0f;
                    acc[mt][nt][half * 2 + 1] = 0.0f;
                }
            }
        }
    };

    // prime: group0 = ACT + B(0) -> buf0, group1 = B(1) -> buf1
    loadACT();
    prefetchB(0, 0);
    CP_COMMIT();
    prefetchB(1, 1);
    CP_COMMIT();

    // 24 chunks: g = L*8 + c, L in {0(W2),1(W3),2(W4)}; buffer = g%3
    for (int g = 0; g < 24; g++) {
        if (g < 23) { CP_WAIT1(); } else { CP_WAIT0(); }
        __syncthreads();
        compute(sb + ACT_HI + (uint32_t)(g & 7) * 64, sb + BBUF + (g % 3) * 40960);
        if (g + 2 < 24) {
            prefetchB(g + 2, (g + 2) % 3);
            CP_COMMIT();
        }
        if ((g & 7) == 7) {
            int L = g >> 3;
            __syncthreads();  // all warps done reading ACT for this layer
            if (L < 2) {
                epilogue_act(L);
                // next-iteration top sync publishes the new ACT
            } else {
                // final: bias -> fp32 rows in SMEM (reuse ACT area), bulk-reduce
#pragma unroll
                for (int mt = 0; mt < 2; mt++) {
#pragma unroll
                    for (int nt = 0; nt < 8; nt++) {
                        int ra = r0 + mt * 16 + (lane >> 2);
                        int ca = c0 + nt * 8 + 2 * (lane & 3);
                        float bv0 = s_bias[512 + ca], bv1 = s_bias[512 + ca + 1];
#pragma unroll
                        for (int half = 0; half < 2; half++) {
                            int r = ra + half * 8;
                            float2 v;
                            v.x = acc[mt][nt][half * 2 + 0] + bv0;
                            v.y = acc[mt][nt][half * 2 + 1] + bv1;
                            *(float2*)(dsm + (uint32_t)r * 1024 + (uint32_t)ca * 4) = v;
                        }
                    }
                }
                FENCE_ASYNC();
                __syncthreads();
                if (tid < 64 && (e0 + tid) < E) {
                    bulk_reduce_add_f32(agg + (size_t)s_dst[tid] * 256,
                                        sb + (uint32_t)tid * 1024, 1024);
                }
                BULK_COMMIT();
                BULK_WAIT0();
            }
        }
    }
}

// ---------------------------------------------------------------------------
extern "C" void kernel_launch(void* const* d_in, const int* in_sizes, int n_in,
                              void* d_out, int out_size) {
    const int* atom_types = (const int*)d_in[0];
    const float* x_extra = (const float*)d_in[1];
    const int* edge_index = (const int*)d_in[2];
    const float* dists = (const float*)d_in[3];
    const float* freq = (const float*)d_in[4];
    const float* emb_table = (const float*)d_in[5];
    const float* w_emb = (const float*)d_in[6];
    const float* b_emb = (const float*)d_in[7];
    const float* w_n2m = (const float*)d_in[8];
    const float* b_n2m = (const float*)d_in[9];
    const float* w_r2m = (const float*)d_in[10];
    const float* b_r2m = (const float*)d_in[11];
    const float* w_m2n = (const float*)d_in[12];
    const float* mw1 = (const float*)d_in[13];
    const float* mb1 = (const float*)d_in[14];
    const float* mw2 = (const float*)d_in[15];
    const float* mb2 = (const float*)d_in[16];
    const float* mw3 = (const float*)d_in[17];
    const float* mb3 = (const float*)d_in[18];
    const float* mw4 = (const float*)d_in[19];
    const float* mb4 = (const float*)d_in[20];
    const float* fw1 = (const float*)d_in[21];
    const float* fb1 = (const float*)d_in[22];
    const float* fw2 = (const float*)d_in[23];
    const float* fb2 = (const float*)d_in[24];
    float* out = (float*)d_out;

    int N = in_sizes[0];
    int E = in_sizes[2] / 2;

    float *p_xcat, *p_h, *p_p, *p_q, *p_agg, *p_t, *p_u;
    float *p_wpa, *p_wqb, *p_wr2, *p_cz;
    __nv_bfloat16 *p_a1h, *p_a1l, *p_wt;
    cudaGetSymbolAddress((void**)&p_xcat, g_xcat);
    cudaGetSymbolAddress((void**)&p_h, g_h);
    cudaGetSymbolAddress((void**)&p_p, g_p);
    cudaGetSymbolAddress((void**)&p_q, g_q);
    cudaGetSymbolAddress((void**)&p_agg, g_agg);
    cudaGetSymbolAddress((void**)&p_t, g_t);
    cudaGetSymbolAddress((void**)&p_u, g_u);
    cudaGetSymbolAddress((void**)&p_wpa, g_wpa);
    cudaGetSymbolAddress((void**)&p_wqb, g_wqb);
    cudaGetSymbolAddress((void**)&p_wr2, g_wr2);
    cudaGetSymbolAddress((void**)&p_cz, g_cz);
    cudaGetSymbolAddress((void**)&p_a1h, g_a1h);
    cudaGetSymbolAddress((void**)&p_a1l, g_a1l);
    cudaGetSymbolAddress((void**)&p_wt, g_wt);

    cudaFuncSetAttribute(edge_mlp_hmma, cudaFuncAttributeMaxDynamicSharedMemorySize, DSMEM);

    dim3 gN((N + 63) / 64, 2);
    dim3 gFold(4, 2, 2), g32(1, 2);
    int gE64 = (E + 63) / 64;

    // weight folding preps (wpa & wqb in one launch via blockIdx.z)
    gemm_bn128<<<gFold, 256>>>(w_n2m, 256, mw1, nullptr, nullptr, p_wpa, 256, 0,
                               mw1 + 256 * 256, p_wqb);
    gemm_bn128<<<g32, 256>>>(w_r2m, 256, mw1 + 512 * 256, nullptr, nullptr, p_wr2, 32, 0,
                             nullptr, nullptr);
    cz_kernel<<<256, 256>>>(b_n2m, b_r2m, mb1, mw1, p_cz);
    wprep_kernel<<<768, 256>>>(mw2, mw3, mw4, p_wt);

    // node pipeline
    xcat_kernel<<<(N * 48 + 255) / 256, 256>>>(atom_types, x_extra, emb_table, p_xcat, N);
    gemm_bn128<<<gN, 256>>>(p_xcat, 48, w_emb, b_emb, nullptr, p_h, N, 1, nullptr, nullptr);
    gemm_bn128<<<gN, 256>>>(p_h, 256, p_wpa, nullptr, nullptr, p_p, N, 0, nullptr, nullptr);
    gemm_bn128<<<gN, 256>>>(p_h, 256, p_wqb, nullptr, nullptr, p_q, N, 0, nullptr, nullptr);

    // edge pipeline
    edge_combine<<<gE64, 256>>>(dists, freq, p_wr2, p_p, p_q, p_cz, edge_index,
                                p_a1h, p_a1l, E);
    cudaMemsetAsync(p_agg, 0, (size_t)N * 256 * sizeof(float));
    edge_mlp_hmma<<<gE64, 256, DSMEM>>>(p_a1h, p_a1l, edge_index, p_wt,
                                        mb2, mb3, mb4, p_agg, E);

    // output
    gemm_bn128<<<gN, 256>>>(p_agg, 256, w_m2n, nullptr, p_h, p_t, N, 0, nullptr, nullptr);
    gemm_bn128<<<gN, 256>>>(p_t, 256, fw1, fb1, nullptr, p_u, N, 1, nullptr, nullptr);
    gemm_bn128<<<gN, 256>>>(p_u, 256, fw2, fb2, p_t, out, N, 0, nullptr, nullptr);
}

// round 8
// speedup vs baseline: 3.5984x; 1.1563x over previous
#include <cuda_runtime.h>
#include <cuda_bf16.h>
#include <math.h>
#include <stdint.h>

#define NN 10000
#define EE 160000
#define HH 256

// ---------------------------------------------------------------------------
// Scratch (no runtime allocation allowed)
// ---------------------------------------------------------------------------
__device__ float g_xcat[NN * 48];
__device__ float g_h[NN * HH];
__device__ float g_p[NN * HH];
__device__ float g_q[NN * HH];
__device__ float g_agg[NN * HH];
__device__ float g_t[NN * HH];
__device__ float g_u[NN * HH];
__device__ float g_wpa[256 * 256];
__device__ float g_wqb[256 * 256];
__device__ float g_wr2[32 * 256];
__device__ float g_cz[256];
// act1 (layer-1 activations) hi/lo bf16, [E, 256]
__device__ __nv_bfloat16 g_a1h[(size_t)EE * HH];
__device__ __nv_bfloat16 g_a1l[(size_t)EE * HH];
// Transposed weights W^T[N=256, K=256] K-major, per Kc=32 chunk.
// 24 tiles (L2: 0..7, L3: 8..15, L4: 16..23); tile = 8192 hi then 8192 lo bf16
__device__ __align__(16) __nv_bfloat16 g_wt[24 * 16384];

__device__ __forceinline__ float gelu_f(float x) {
    float x3 = x * x * x;
    return 0.5f * x * (1.0f + tanhf(0.7978845608028654f * (x + 0.044715f * x3)));
}
__device__ __forceinline__ float lrelu_f(float x) { return x > 0.0f ? x : 0.01f * x; }

// ---------------------------------------------------------------------------
// PTX helpers (sm_80/sm_90 base ISA: valid at .target sm_100)
// ---------------------------------------------------------------------------
__device__ __forceinline__ uint32_t smem_u32(const void* p) {
    uint32_t a;
    asm("{ .reg .u64 t; cvta.to.shared.u64 t, %1; cvt.u32.u64 %0, t; }" : "=r"(a) : "l"(p));
    return a;
}
__device__ __forceinline__ void cp_async16(uint32_t smem_addr, const void* gptr) {
    asm volatile("cp.async.cg.shared.global [%0], [%1], 16;\n" :: "r"(smem_addr), "l"(gptr));
}
#define CP_COMMIT() asm volatile("cp.async.commit_group;\n" ::: "memory")
#define CP_WAIT0()  asm volatile("cp.async.wait_group 0;\n" ::: "memory")
#define CP_WAIT1()  asm volatile("cp.async.wait_group 1;\n" ::: "memory")

// SMEM -> GMEM bulk reduction (sm_90 base ISA)
__device__ __forceinline__ void bulk_reduce_add_f32(void* gdst, uint32_t ssrc, uint32_t bytes) {
    asm volatile("cp.reduce.async.bulk.global.shared::cta.bulk_group.add.f32 [%0], [%1], %2;\n"
                 :: "l"(gdst), "r"(ssrc), "r"(bytes) : "memory");
}
#define BULK_COMMIT() asm volatile("cp.async.bulk.commit_group;" ::: "memory")
#define BULK_WAIT0()  asm volatile("cp.async.bulk.wait_group 0;" ::: "memory")
#define FENCE_ASYNC() asm volatile("fence.proxy.async.shared::cta;" ::: "memory")

__device__ __forceinline__ void ldsm4(uint32_t* f, uint32_t a) {
    asm volatile("ldmatrix.sync.aligned.m8n8.x4.shared.b16 {%0,%1,%2,%3}, [%4];\n"
                 : "=r"(f[0]), "=r"(f[1]), "=r"(f[2]), "=r"(f[3]) : "r"(a));
}
__device__ __forceinline__ void mma16816(float* d, const uint32_t* a, uint32_t b0, uint32_t b1) {
    asm volatile(
        "mma.sync.aligned.m16n8k16.row.col.f32.bf16.bf16.f32 "
        "{%0,%1,%2,%3}, {%4,%5,%6,%7}, {%8,%9}, {%0,%1,%2,%3};\n"
        : "+f"(d[0]), "+f"(d[1]), "+f"(d[2]), "+f"(d[3])
        : "r"(a[0]), "r"(a[1]), "r"(a[2]), "r"(a[3]), "r"(b0), "r"(b1));
}

// ---------------------------------------------------------------------------
// Node-side GEMM, BM=64, BN=128 (gridDim.y=2), BK=32; optional second (W,C)
// pair selected by blockIdx.z.
// ---------------------------------------------------------------------------
__global__ __launch_bounds__(256, 2) void gemm_bn128(
    const float* __restrict__ A, int K, const float* __restrict__ W,
    const float* __restrict__ bias, const float* __restrict__ res,
    float* __restrict__ C, int rows, int act,
    const float* __restrict__ W2, float* __restrict__ C2) {
    __shared__ float As[64 * 33];
    __shared__ float Bs[32 * 132];
    if (blockIdx.z == 1) { W = W2; C = C2; }
    int tid = threadIdx.x, tx = tid & 15, ty = tid >> 4;
    int row0 = blockIdx.x * 64;
    int col0 = blockIdx.y * 128;
    float acc[4][8];
#pragma unroll
    for (int i = 0; i < 4; i++)
#pragma unroll
        for (int j = 0; j < 8; j++) acc[i][j] = 0.0f;
    for (int k0 = 0; k0 < K; k0 += 32) {
#pragma unroll
        for (int i = 0; i < 8; i++) {
            int idx = tid + i * 256, r = idx >> 5, c = idx & 31;
            int gr = row0 + r, gk = k0 + c;
            As[r * 33 + c] = (gr < rows && gk < K) ? A[(long)gr * K + gk] : 0.0f;
        }
#pragma unroll
        for (int i = 0; i < 16; i++) {
            int idx = tid + i * 256, r = idx >> 7, c = idx & 127;
            int gk = k0 + r;
            Bs[r * 132 + c] = (gk < K) ? W[(long)gk * 256 + col0 + c] : 0.0f;
        }
        __syncthreads();
#pragma unroll
        for (int kk = 0; kk < 32; kk++) {
            float a[4];
#pragma unroll
            for (int i = 0; i < 4; i++) a[i] = As[(ty * 4 + i) * 33 + kk];
#pragma unroll
            for (int j = 0; j < 8; j++) {
                float b = Bs[kk * 132 + tx + 16 * j];
#pragma unroll
                for (int i = 0; i < 4; i++) acc[i][j] = fmaf(a[i], b, acc[i][j]);
            }
        }
        __syncthreads();
    }
#pragma unroll
    for (int i = 0; i < 4; i++) {
        int r = row0 + ty * 4 + i;
        if (r < rows) {
#pragma unroll
            for (int j = 0; j < 8; j++) {
                int col = col0 + tx + 16 * j;
                float v = acc[i][j];
                if (bias) v += bias[col];
                if (act == 1) v = gelu_f(v);
                if (res) v += res[(long)r * 256 + col];
                C[(long)r * 256 + col] = v;
            }
        }
    }
}

// ---------------------------------------------------------------------------
// Small prep kernels
// ---------------------------------------------------------------------------
__global__ void xcat_kernel(const int* __restrict__ atom_types,
                            const float* __restrict__ x_extra,
                            const float* __restrict__ emb_table,
                            float* __restrict__ xcat, int N) {
    int idx = blockIdx.x * blockDim.x + threadIdx.x;
    if (idx < N * 48) {
        int n = idx / 48, c = idx - n * 48;
        xcat[idx] = (c < 32) ? emb_table[atom_types[n] * 32 + c] : x_extra[n * 16 + (c - 32)];
    }
}

// cz[n] = b_n2m @ (W1a + W1b) + b_r2m @ W1c + b1  -- one block per n, parallel-k
__global__ void cz_kernel(const float* __restrict__ b_n2m, const float* __restrict__ b_r2m,
                          const float* __restrict__ b1, const float* __restrict__ w1,
                          float* __restrict__ cz) {
    __shared__ float red[256];
    int n = blockIdx.x, k = threadIdx.x;
    float s = b_n2m[k] * (w1[k * 256 + n] + w1[(256 + k) * 256 + n]);
    s += b_r2m[k] * w1[(512 + k) * 256 + n];
    red[k] = s;
    __syncthreads();
    for (int st = 128; st > 0; st >>= 1) {
        if (k < st) red[k] += red[k + st];
        __syncthreads();
    }
    if (k == 0) cz[n] = red[0] + b1[n];
}

// mlp_w2/3/4 -> W^T hi/lo chunk tiles (24 tiles)
__global__ void wprep_kernel(const float* __restrict__ w2, const float* __restrict__ w3,
                             const float* __restrict__ w4, __nv_bfloat16* __restrict__ wt) {
    int id = blockIdx.x * blockDim.x + threadIdx.x;
    if (id >= 768 * 256) return;
    int kg = id >> 8, n = id & 255;
    const float* w;
    int kl, t;
    if (kg < 256)      { w = w2; kl = kg;       t = kl >> 5; }
    else if (kg < 512) { w = w3; kl = kg - 256; t = 8 + (kl >> 5); }
    else               { w = w4; kl = kg - 512; t = 16 + (kl >> 5); }
    int kk = kl & 31;
    float v = w[(long)kl * 256 + n];
    __nv_bfloat16 h = __float2bfloat16(v);
    __nv_bfloat16 l = __float2bfloat16(v - __bfloat162float(h));
    size_t base = (size_t)t * 16384 + n * 32 + kk;
    wt[base] = h;
    wt[base + 8192] = l;
}

// ---------------------------------------------------------------------------
// edge combine: act1 = lrelu( rbf@Wr2 + p[src] + q[dst] + cz ) -> bf16 hi/lo
// ---------------------------------------------------------------------------
__global__ __launch_bounds__(256, 2) void edge_combine(
    const float* __restrict__ dists, const float* __restrict__ freq,
    const float* __restrict__ wr2, const float* __restrict__ p,
    const float* __restrict__ q, const float* __restrict__ cz,
    const int* __restrict__ edge_index,
    __nv_bfloat16* __restrict__ a1h, __nv_bfloat16* __restrict__ a1l, int E) {
    __shared__ float Rs[64 * 33];
    __shared__ float Bs[32 * 256];
    __shared__ float s_freq[32];
    __shared__ float s_cz[256];
    __shared__ int s_src[64], s_dst[64];
    int tid = threadIdx.x, tx = tid & 15, ty = tid >> 4;
    int e0 = blockIdx.x * 64;
    if (tid < 32) s_freq[tid] = freq[tid];
    s_cz[tid] = cz[tid];
    if (tid < 64) {
        int e = e0 + tid;
        s_src[tid] = (e < E) ? edge_index[e] : 0;
        s_dst[tid] = (e < E) ? edge_index[E + e] : 0;
    }
#pragma unroll
    for (int i = 0; i < 32; i++) Bs[i * 256 + tid] = wr2[i * 256 + tid];
    __syncthreads();
#pragma unroll
    for (int i = 0; i < 8; i++) {
        int idx = tid + i * 256, el = idx >> 5, r = idx & 31;
        int e = e0 + el;
        float d = (e < E) ? dists[e] * 0.2f : 1.0f;
        float d2 = d * d, d5 = d2 * d2 * d;
        float env = 1.0f / d + d5 * (-28.0f + d * (48.0f + d * (-21.0f)));
        Rs[el * 33 + r] = env * sinf(s_freq[r] * d);
    }
    __syncthreads();
    float acc[4][16];
#pragma unroll
    for (int i = 0; i < 4; i++)
#pragma unroll
        for (int j = 0; j < 16; j++) acc[i][j] = 0.0f;
#pragma unroll
    for (int kk = 0; kk < 32; kk++) {
        float a[4];
#pragma unroll
        for (int i = 0; i < 4; i++) a[i] = Rs[(ty * 4 + i) * 33 + kk];
#pragma unroll
        for (int j = 0; j < 16; j++) {
            float b = Bs[kk * 256 + tx + 16 * j];
#pragma unroll
            for (int i = 0; i < 4; i++) acc[i][j] = fmaf(a[i], b, acc[i][j]);
        }
    }
#pragma unroll
    for (int i = 0; i < 4; i++) {
        int r = ty * 4 + i;
        int e = e0 + r;
        if (e < E) {
            const float* prow = p + (size_t)s_src[r] * 256;
            const float* qrow = q + (size_t)s_dst[r] * 256;
#pragma unroll
            for (int j = 0; j < 16; j++) {
                int col = tx + 16 * j;
                float v = acc[i][j] + prow[col] + qrow[col] + s_cz[col];
                v = lrelu_f(v);
                __nv_bfloat16 h = __float2bfloat16(v);
                a1h[(size_t)e * 256 + col] = h;
                a1l[(size_t)e * 256 + col] = __float2bfloat16(v - __bfloat162float(h));
            }
        }
    }
}

// ---------------------------------------------------------------------------
// HMMA fused edge MLP (layers 2..4). CTA = 128 edges x 256 outputs, 16 warps
// (4x4 warp grid, warp tile 32x64), 2-deep B ring (dist-1 prefetch).
// Inner loop keeps ONE B-fragment quartet live (reg pressure at 512 thr).
// Final layer: fp32 rows in SMEM -> cp.reduce.async.bulk scatter.
// Dynamic SMEM:
//   ACT_HI [0,      67584) : 128 rows x 264 bf16 (stride 528B)  (also FOUT fp32)
//   ACT_LO [67584, 135168)
//   BBUF   [135168,217088): 2 x (hi 256x40 bf16 stride 80B | lo +20480)
// ---------------------------------------------------------------------------
#define ACT_HI 0
#define ACT_LO 67584
#define BBUF   135168
#define DSMEM  217088

__global__ __launch_bounds__(512, 1) void edge_mlp_hmma(
    const __nv_bfloat16* __restrict__ a1h, const __nv_bfloat16* __restrict__ a1l,
    const int* __restrict__ edge_index, const __nv_bfloat16* __restrict__ wt,
    const float* __restrict__ b2, const float* __restrict__ b3,
    const float* __restrict__ b4, float* __restrict__ agg, int E) {
    extern __shared__ __align__(16) char dsm[];
    __shared__ int s_dst[128];
    __shared__ float s_bias[768];

    const int tid = threadIdx.x;
    const int wid = tid >> 5, lane = tid & 31;
    const int wm = wid >> 2, wn = wid & 3;
    const int r0 = wm * 32;        // 4 M-warps x 32 = 128 edges
    const int c0 = wn * 64;        // 4 N-warps x 64 = 256 cols
    const int e0 = blockIdx.x * 128;
    const uint32_t sb = smem_u32(dsm);

    for (int i = tid; i < 768; i += 512) {
        const float* b = (i < 256) ? b2 : (i < 512) ? b3 : b4;
        s_bias[i] = b[i & 255];
    }
    if (tid < 128) {
        int e = e0 + tid;
        s_dst[tid] = (e < E) ? edge_index[E + e] : 0;
    }

    float acc[2][8][4];
#pragma unroll
    for (int mt = 0; mt < 2; mt++)
#pragma unroll
        for (int nt = 0; nt < 8; nt++)
#pragma unroll
            for (int i = 0; i < 4; i++) acc[mt][nt][i] = 0.0f;

    auto prefetchB = [&](int t, int buf) {
        const char* wsrc = (const char*)wt + (size_t)t * 32768;
        uint32_t dbase = sb + BBUF + buf * 40960;
#pragma unroll
        for (int it = 0; it < 4; it++) {
            int id = tid + it * 512;
            int n = id & 255, rest = id >> 8;   // rest in 0..7
            int seg = rest & 3, hl = rest >> 2;
            cp_async16(dbase + hl * 20480 + n * 80 + seg * 16,
                       wsrc + hl * 16384 + n * 64 + seg * 16);
        }
    };
    auto loadACT = [&]() {
#pragma unroll
        for (int it = 0; it < 16; it++) {
            int id = tid + it * 512;            // 0..8191
            int seg = id & 31;
            int hl = (id >> 5) & 1;
            int row = id >> 6;                  // 0..127
            int e = e0 + row;
            if (e >= E) e = E - 1;
            const char* sp = (const char*)(hl ? a1l : a1h) + (size_t)e * 512 + seg * 16;
            cp_async16(sb + (hl ? ACT_LO : ACT_HI) + (uint32_t)row * 528 + seg * 16, sp);
        }
    };
    auto compute = [&](uint32_t abase, uint32_t bbase) {
#pragma unroll
        for (int s = 0; s < 2; s++) {
            int ko2 = s * 32;
            uint32_t ah[2][4], al[2][4];
#pragma unroll
            for (int mt = 0; mt < 2; mt++) {
                uint32_t ad = abase + (uint32_t)(r0 + mt * 16 + (lane & 15)) * 528 +
                              ko2 + ((lane >> 4) << 4);
                ldsm4(ah[mt], ad);
                ldsm4(al[mt], ad + (ACT_LO - ACT_HI));
            }
#pragma unroll
            for (int q = 0; q < 4; q++) {
                int n = c0 + q * 16 + (lane & 7) + ((lane & 16) >> 1);
                uint32_t bd = bbase + (uint32_t)n * 80 + ko2 + ((lane & 8) << 1);
                uint32_t bh[4], bl[4];
                ldsm4(bh, bd);
                ldsm4(bl, bd + 20480);
#pragma unroll
                for (int mt = 0; mt < 2; mt++) {
                    mma16816(acc[mt][2 * q + 0], ah[mt], bh[0], bh[1]);
                    mma16816(acc[mt][2 * q + 1], ah[mt], bh[2], bh[3]);
                    mma16816(acc[mt][2 * q + 0], al[mt], bh[0], bh[1]);
                    mma16816(acc[mt][2 * q + 1], al[mt], bh[2], bh[3]);
                    mma16816(acc[mt][2 * q + 0], ah[mt], bl[0], bl[1]);
                    mma16816(acc[mt][2 * q + 1], ah[mt], bl[2], bl[3]);
                }
            }
        }
    };
    auto epilogue_act = [&](int bidx) {
#pragma unroll
        for (int mt = 0; mt < 2; mt++) {
#pragma unroll
            for (int nt = 0; nt < 8; nt++) {
                int ra = r0 + mt * 16 + (lane >> 2);
                int ca = c0 + nt * 8 + 2 * (lane & 3);
                float bv0 = s_bias[bidx * 256 + ca], bv1 = s_bias[bidx * 256 + ca + 1];
#pragma unroll
                for (int half = 0; half < 2; half++) {
                    int r = ra + half * 8;
                    float v0 = lrelu_f(acc[mt][nt][half * 2 + 0] + bv0);
                    float v1 = lrelu_f(acc[mt][nt][half * 2 + 1] + bv1);
                    __nv_bfloat16 h0 = __float2bfloat16(v0);
                    __nv_bfloat16 h1 = __float2bfloat16(v1);
                    __nv_bfloat162 hp; hp.x = h0; hp.y = h1;
                    __nv_bfloat162 lp;
                    lp.x = __float2bfloat16(v0 - __bfloat162float(h0));
                    lp.y = __float2bfloat16(v1 - __bfloat162float(h1));
                    uint32_t off = (uint32_t)r * 528 + (uint32_t)ca * 2;
                    *(__nv_bfloat162*)(dsm + ACT_HI + off) = hp;
                    *(__nv_bfloat162*)(dsm + ACT_LO + off) = lp;
                    acc[mt][nt][half * 2 + 0] = 0.0f;
                    acc[mt][nt][half * 2 + 1] = 0.0f;
                }
            }
        }
    };

    // prime: group0 = ACT + B(0) -> buf0, group1 = B(1) -> buf1
    loadACT();
    prefetchB(0, 0);
    CP_COMMIT();
    prefetchB(1, 1);
    CP_COMMIT();

    // 24 chunks: g = L*8 + c, L in {0(W2),1(W3),2(W4)}; buffer = g&1
    for (int g = 0; g < 24; g++) {
        if (g < 23) { CP_WAIT1(); } else { CP_WAIT0(); }
        __syncthreads();                  // B(g) (and ACT at g=0) visible to all
        compute(sb + ACT_HI + (uint32_t)(g & 7) * 64, sb + BBUF + (g & 1) * 40960);
        __syncthreads();                  // all done reading buf g&1 / layer ACT
        if (g + 2 < 24) {
            prefetchB(g + 2, g & 1);
            CP_COMMIT();
        }
        if ((g & 7) == 7) {
            int L = g >> 3;
            if (L < 2) {
                epilogue_act(L);
                // next-iteration top sync publishes the new ACT
            } else {
                // final: bias -> fp32 rows in SMEM (reuse ACT area), bulk-reduce
#pragma unroll
                for (int mt = 0; mt < 2; mt++) {
#pragma unroll
                    for (int nt = 0; nt < 8; nt++) {
                        int ra = r0 + mt * 16 + (lane >> 2);
                        int ca = c0 + nt * 8 + 2 * (lane & 3);
                        float bv0 = s_bias[512 + ca], bv1 = s_bias[512 + ca + 1];
#pragma unroll
                        for (int half = 0; half < 2; half++) {
                            int r = ra + half * 8;
                            float2 v;
                            v.x = acc[mt][nt][half * 2 + 0] + bv0;
                            v.y = acc[mt][nt][half * 2 + 1] + bv1;
                            *(float2*)(dsm + (uint32_t)r * 1024 + (uint32_t)ca * 4) = v;
                        }
                    }
                }
                FENCE_ASYNC();
                __syncthreads();
                if (tid < 128 && (e0 + tid) < E) {
                    bulk_reduce_add_f32(agg + (size_t)s_dst[tid] * 256,
                                        sb + (uint32_t)tid * 1024, 1024);
                }
                BULK_COMMIT();
                BULK_WAIT0();
            }
        }
    }
}

// ---------------------------------------------------------------------------
extern "C" void kernel_launch(void* const* d_in, const int* in_sizes, int n_in,
                              void* d_out, int out_size) {
    const int* atom_types = (const int*)d_in[0];
    const float* x_extra = (const float*)d_in[1];
    const int* edge_index = (const int*)d_in[2];
    const float* dists = (const float*)d_in[3];
    const float* freq = (const float*)d_in[4];
    const float* emb_table = (const float*)d_in[5];
    const float* w_emb = (const float*)d_in[6];
    const float* b_emb = (const float*)d_in[7];
    const float* w_n2m = (const float*)d_in[8];
    const float* b_n2m = (const float*)d_in[9];
    const float* w_r2m = (const float*)d_in[10];
    const float* b_r2m = (const float*)d_in[11];
    const float* w_m2n = (const float*)d_in[12];
    const float* mw1 = (const float*)d_in[13];
    const float* mb1 = (const float*)d_in[14];
    const float* mw2 = (const float*)d_in[15];
    const float* mb2 = (const float*)d_in[16];
    const float* mw3 = (const float*)d_in[17];
    const float* mb3 = (const float*)d_in[18];
    const float* mw4 = (const float*)d_in[19];
    const float* mb4 = (const float*)d_in[20];
    const float* fw1 = (const float*)d_in[21];
    const float* fb1 = (const float*)d_in[22];
    const float* fw2 = (const float*)d_in[23];
    const float* fb2 = (const float*)d_in[24];
    float* out = (float*)d_out;

    int N = in_sizes[0];
    int E = in_sizes[2] / 2;

    float *p_xcat, *p_h, *p_p, *p_q, *p_agg, *p_t, *p_u;
    float *p_wpa, *p_wqb, *p_wr2, *p_cz;
    __nv_bfloat16 *p_a1h, *p_a1l, *p_wt;
    cudaGetSymbolAddress((void**)&p_xcat, g_xcat);
    cudaGetSymbolAddress((void**)&p_h, g_h);
    cudaGetSymbolAddress((void**)&p_p, g_p);
    cudaGetSymbolAddress((void**)&p_q, g_q);
    cudaGetSymbolAddress((void**)&p_agg, g_agg);
    cudaGetSymbolAddress((void**)&p_t, g_t);
    cudaGetSymbolAddress((void**)&p_u, g_u);
    cudaGetSymbolAddress((void**)&p_wpa, g_wpa);
    cudaGetSymbolAddress((void**)&p_wqb, g_wqb);
    cudaGetSymbolAddress((void**)&p_wr2, g_wr2);
    cudaGetSymbolAddress((void**)&p_cz, g_cz);
    cudaGetSymbolAddress((void**)&p_a1h, g_a1h);
    cudaGetSymbolAddress((void**)&p_a1l, g_a1l);
    cudaGetSymbolAddress((void**)&p_wt, g_wt);

    cudaFuncSetAttribute(edge_mlp_hmma, cudaFuncAttributeMaxDynamicSharedMemorySize, DSMEM);

    dim3 gN((N + 63) / 64, 2);
    dim3 gPQ((N + 63) / 64, 2, 2);
    dim3 gFold(4, 2, 2), g32(1, 2);
    int gE64 = (E + 63) / 64;
    int gE128 = (E + 127) / 128;

    // weight folding preps (wpa & wqb in one launch via blockIdx.z)
    gemm_bn128<<<gFold, 256>>>(w_n2m, 256, mw1, nullptr, nullptr, p_wpa, 256, 0,
                               mw1 + 256 * 256, p_wqb);
    gemm_bn128<<<g32, 256>>>(w_r2m, 256, mw1 + 512 * 256, nullptr, nullptr, p_wr2, 32, 0,
                             nullptr, nullptr);
    cz_kernel<<<256, 256>>>(b_n2m, b_r2m, mb1, mw1, p_cz);
    wprep_kernel<<<768, 256>>>(mw2, mw3, mw4, p_wt);

    // node pipeline
    xcat_kernel<<<(N * 48 + 255) / 256, 256>>>(atom_types, x_extra, emb_table, p_xcat, N);
    gemm_bn128<<<gN, 256>>>(p_xcat, 48, w_emb, b_emb, nullptr, p_h, N, 1, nullptr, nullptr);
    gemm_bn128<<<gPQ, 256>>>(p_h, 256, p_wpa, nullptr, nullptr, p_p, N, 0, p_wqb, p_q);

    // edge pipeline
    edge_combine<<<gE64, 256>>>(dists, freq, p_wr2, p_p, p_q, p_cz, edge_index,
                                p_a1h, p_a1l, E);
    cudaMemsetAsync(p_agg, 0, (size_t)N * 256 * sizeof(float));
    edge_mlp_hmma<<<gE128, 512, DSMEM>>>(p_a1h, p_a1l, edge_index, p_wt,
                                         mb2, mb3, mb4, p_agg, E);

    // output
    gemm_bn128<<<gN, 256>>>(p_agg, 256, w_m2n, nullptr, p_h, p_t, N, 0, nullptr, nullptr);
    gemm_bn128<<<gN, 256>>>(p_t, 256, fw1, fb1, nullptr, p_u, N, 1, nullptr, nullptr);
    gemm_bn128<<<gN, 256>>>(p_u, 256, fw2, fb2, p_t, out, N, 0, nullptr, nullptr);
}